// round 2
// baseline (speedup 1.0000x reference)
#include <cuda_runtime.h>
#include <math.h>

#define BB     4096
#define LATENT 128
#define HH     256
#define G4     1024   // 4*HH
#define OUTN   88
#define TT     64
#define LL     5

// ---------------- static device scratch (no allocations allowed) -------------
__device__ float g_h[LL * 2 * BB * HH];          // per-layer h, parity double-buffered (40 MB)
__device__ float g_c[LL * BB * HH];              // per-layer c                          (20 MB)
__device__ float g_xp[BB * HH];                  // x @ linear_w.T + b                   ( 4 MB)
__device__ float g_gx0[BB * G4];                 // layer-0 input gates (const in t)     (16 MB)
__device__ float g_ys[BB * TT * HH];             // h of top layer, [B][T][H]            (268 MB)

// ---------------------------------------------------------------------------
__global__ void zero_kernel(float* __restrict__ p, int n) {
    int i = blockIdx.x * blockDim.x + threadIdx.x;
    int stride = gridDim.x * blockDim.x;
    for (; i < n; i += stride) p[i] = 0.0f;
}

__device__ __forceinline__ float sigf(float x) { return 1.0f / (1.0f + expf(-x)); }

// ---------------------------------------------------------------------------
// Generic tiled GEMM: C[m,n] = act( sum_k A[m,k]*Wt[n,k] + bias[n] )
// A row-major [M,K], Wt row-major [N,K]. BM=BN=64, BK=8, 256 threads, 4x4/thread.
// M, K must be multiples of 64 / 8. N may be ragged (guarded).
template <bool SIG>
__global__ __launch_bounds__(256) void gemm_bias_kernel(
    const float* __restrict__ A, const float* __restrict__ Wt,
    const float* __restrict__ bias, float* __restrict__ C,
    int M, int N, int K, int ldc)
{
    __shared__ float As[2][8][64];
    __shared__ float Bs[2][8][64];
    const int tid = threadIdx.x;
    const int tx = tid & 15, ty = tid >> 4;
    const int m0 = blockIdx.y * 64, n0 = blockIdx.x * 64;
    const int lr = tid >> 2, lc = (tid & 3) * 2;

    float acc[4][4] = {};

    auto load = [&](int tile, int buf) {
        int kt = tile * 8;
        float2 a2 = *reinterpret_cast<const float2*>(A + (size_t)(m0 + lr) * K + kt + lc);
        As[buf][lc][lr] = a2.x; As[buf][lc + 1][lr] = a2.y;
        float2 b2 = make_float2(0.0f, 0.0f);
        if (n0 + lr < N)
            b2 = *reinterpret_cast<const float2*>(Wt + (size_t)(n0 + lr) * K + kt + lc);
        Bs[buf][lc][lr] = b2.x; Bs[buf][lc + 1][lr] = b2.y;
    };

    const int ntiles = K >> 3;
    load(0, 0);
    __syncthreads();
    for (int tile = 0; tile < ntiles; ++tile) {
        int cur = tile & 1;
        if (tile + 1 < ntiles) load(tile + 1, cur ^ 1);
#pragma unroll
        for (int kk = 0; kk < 8; ++kk) {
            float4 av = *reinterpret_cast<const float4*>(&As[cur][kk][ty * 4]);
            float4 bv = *reinterpret_cast<const float4*>(&Bs[cur][kk][tx * 4]);
            float a[4] = {av.x, av.y, av.z, av.w};
            float b[4] = {bv.x, bv.y, bv.z, bv.w};
#pragma unroll
            for (int mi = 0; mi < 4; ++mi)
#pragma unroll
                for (int ni = 0; ni < 4; ++ni)
                    acc[mi][ni] += a[mi] * b[ni];
        }
        __syncthreads();
    }

#pragma unroll
    for (int mi = 0; mi < 4; ++mi) {
        int row = m0 + ty * 4 + mi;
#pragma unroll
        for (int ni = 0; ni < 4; ++ni) {
            int n = n0 + tx * 4 + ni;
            if (n < N) {
                float v = acc[mi][ni] + bias[n];
                if (SIG) v = 1.0f / (1.0f + expf(-v));
                C[(size_t)row * ldc + n] = v;
            }
        }
    }
}

// ---------------------------------------------------------------------------
// Fused LSTM cell: gates[b, g*H+n] = A0[b,:]@W0[g*H+n,:] (+ A1[b,:]@W1[g*H+n,:])
//                                    (+ bih) + bhh (+ gx0), then cell nonlinearity.
// CTA tile: 64 batch x 64 hidden units (x 4 gates). Thread: 4m x 4gate x 4n.
__global__ __launch_bounds__(256, 2) void cell_kernel(
    const float* __restrict__ A0, const float* __restrict__ W0, int K0,
    const float* __restrict__ A1, const float* __restrict__ W1, int K1,
    const float* __restrict__ bih, const float* __restrict__ bhh,
    const float* __restrict__ gx0,
    float* __restrict__ c_state, float* __restrict__ h_out,
    float* __restrict__ ys)
{
    __shared__ float As[2][8][64];
    __shared__ float Bs[2][8][256];
    const int tid = threadIdx.x;
    const int tx = tid & 15, ty = tid >> 4;
    const int m0 = blockIdx.y * 64;
    const int n0 = blockIdx.x * 64;
    const int ar = tid >> 2, ac = (tid & 3) * 2;
    const int gate = tid >> 6, rloc = tid & 63;
    const int wrow = gate * HH + n0 + rloc;   // row within W [4H x H]

    float acc[4][4][4] = {};                   // [mi][gate][ni]

    auto load = [&](int tile, int buf) {
        int kt = tile * 8;
        const float* A = A0; const float* W = W0;
        if (kt >= K0) { A = A1; W = W1; kt -= K0; }
        float2 a2 = *reinterpret_cast<const float2*>(A + (size_t)(m0 + ar) * HH + kt + ac);
        As[buf][ac][ar] = a2.x; As[buf][ac + 1][ar] = a2.y;
        const float4* wp = reinterpret_cast<const float4*>(W + (size_t)wrow * HH + kt);
        float4 w0 = wp[0], w1 = wp[1];
        Bs[buf][0][tid] = w0.x; Bs[buf][1][tid] = w0.y;
        Bs[buf][2][tid] = w0.z; Bs[buf][3][tid] = w0.w;
        Bs[buf][4][tid] = w1.x; Bs[buf][5][tid] = w1.y;
        Bs[buf][6][tid] = w1.z; Bs[buf][7][tid] = w1.w;
    };

    const int ntiles = (K0 + K1) >> 3;
    load(0, 0);
    __syncthreads();
    for (int tile = 0; tile < ntiles; ++tile) {
        int cur = tile & 1;
        if (tile + 1 < ntiles) load(tile + 1, cur ^ 1);
#pragma unroll
        for (int kk = 0; kk < 8; ++kk) {
            float4 av = *reinterpret_cast<const float4*>(&As[cur][kk][ty * 4]);
            float a[4] = {av.x, av.y, av.z, av.w};
#pragma unroll
            for (int g = 0; g < 4; ++g) {
                float4 bv = *reinterpret_cast<const float4*>(&Bs[cur][kk][g * 64 + tx * 4]);
                float b[4] = {bv.x, bv.y, bv.z, bv.w};
#pragma unroll
                for (int mi = 0; mi < 4; ++mi)
#pragma unroll
                    for (int ni = 0; ni < 4; ++ni)
                        acc[mi][g][ni] += a[mi] * b[ni];
            }
        }
        __syncthreads();
    }

    // ---------------- epilogue: bias + LSTM cell ----------------
    const int n = n0 + tx * 4;
    float bsum[4][4];
#pragma unroll
    for (int g = 0; g < 4; ++g) {
        float4 bh = *reinterpret_cast<const float4*>(&bhh[g * HH + n]);
        float4 bi = make_float4(0.f, 0.f, 0.f, 0.f);
        if (bih) bi = *reinterpret_cast<const float4*>(&bih[g * HH + n]);
        bsum[g][0] = bh.x + bi.x; bsum[g][1] = bh.y + bi.y;
        bsum[g][2] = bh.z + bi.z; bsum[g][3] = bh.w + bi.w;
    }

#pragma unroll
    for (int mi = 0; mi < 4; ++mi) {
        int b = m0 + ty * 4 + mi;
        float pre[4][4];
#pragma unroll
        for (int g = 0; g < 4; ++g)
#pragma unroll
            for (int ni = 0; ni < 4; ++ni)
                pre[g][ni] = acc[mi][g][ni] + bsum[g][ni];
        if (gx0) {
#pragma unroll
            for (int g = 0; g < 4; ++g) {
                float4 gx = *reinterpret_cast<const float4*>(&gx0[(size_t)b * G4 + g * HH + n]);
                pre[g][0] += gx.x; pre[g][1] += gx.y; pre[g][2] += gx.z; pre[g][3] += gx.w;
            }
        }
        float4 co4 = *reinterpret_cast<const float4*>(&c_state[(size_t)b * HH + n]);
        float co[4] = {co4.x, co4.y, co4.z, co4.w};
        float cn[4], hn[4];
#pragma unroll
        for (int ni = 0; ni < 4; ++ni) {
            float iv = sigf(pre[0][ni]);
            float fv = sigf(pre[1][ni]);
            float gv = tanhf(pre[2][ni]);
            float ov = sigf(pre[3][ni]);
            cn[ni] = fv * co[ni] + iv * gv;
            hn[ni] = ov * tanhf(cn[ni]);
        }
        *reinterpret_cast<float4*>(&c_state[(size_t)b * HH + n]) = make_float4(cn[0], cn[1], cn[2], cn[3]);
        *reinterpret_cast<float4*>(&h_out[(size_t)b * HH + n])   = make_float4(hn[0], hn[1], hn[2], hn[3]);
        if (ys)
            *reinterpret_cast<float4*>(&ys[(size_t)b * (TT * HH) + n]) = make_float4(hn[0], hn[1], hn[2], hn[3]);
    }
}

// ---------------------------------------------------------------------------
extern "C" void kernel_launch(void* const* d_in, const int* in_sizes, int n_in,
                              void* d_out, int out_size)
{
    const float* x   = (const float*)d_in[0];  // [4096,128]
    const float* lw  = (const float*)d_in[1];  // [256,128]
    const float* lb  = (const float*)d_in[2];  // [256]
    const float* wih = (const float*)d_in[3];  // [5,1024,256]
    const float* whh = (const float*)d_in[4];  // [5,1024,256]
    const float* bih = (const float*)d_in[5];  // [5,1024]
    const float* bhh = (const float*)d_in[6];  // [5,1024]
    const float* ow  = (const float*)d_in[7];  // [88,256]
    const float* ob  = (const float*)d_in[8];  // [88]
    float* out = (float*)d_out;                // [4096,64,88]

    float *hb, *cb, *xp, *gx0, *ys;
    cudaGetSymbolAddress((void**)&hb,  g_h);
    cudaGetSymbolAddress((void**)&cb,  g_c);
    cudaGetSymbolAddress((void**)&xp,  g_xp);
    cudaGetSymbolAddress((void**)&gx0, g_gx0);
    cudaGetSymbolAddress((void**)&ys,  g_ys);

    zero_kernel<<<2048, 256>>>(hb, LL * 2 * BB * HH);
    zero_kernel<<<2048, 256>>>(cb, LL * BB * HH);

    // xp = x @ lw.T + lb            [4096,256]
    gemm_bias_kernel<false><<<dim3(HH / 64, BB / 64), 256>>>(x, lw, lb, xp, BB, HH, LATENT, HH);
    // gx0 = xp @ wih[0].T + bih[0]  [4096,1024]  (constant over time)
    gemm_bias_kernel<false><<<dim3(G4 / 64, BB / 64), 256>>>(xp, wih, bih, gx0, BB, G4, HH, G4);

    const size_t layer_sz = (size_t)BB * HH;
    for (int t = 0; t < TT; ++t) {
        for (int l = 0; l < LL; ++l) {
            float*       h_o    = hb + (size_t)(l * 2 + (t & 1)) * layer_sz;
            const float* h_prev = hb + (size_t)(l * 2 + ((t + 1) & 1)) * layer_sz;
            float*       cst    = cb + (size_t)l * layer_sz;
            float*       ysw    = (l == LL - 1) ? (ys + (size_t)t * HH) : nullptr;
            if (l == 0) {
                cell_kernel<<<dim3(HH / 64, BB / 64), 256>>>(
                    h_prev, whh, HH, nullptr, nullptr, 0,
                    nullptr, bhh, gx0, cst, h_o, ysw);
            } else {
                const float* ain = hb + (size_t)((l - 1) * 2 + (t & 1)) * layer_sz;
                cell_kernel<<<dim3(HH / 64, BB / 64), 256>>>(
                    ain, wih + (size_t)l * G4 * HH, HH,
                    h_prev, whh + (size_t)l * G4 * HH, HH,
                    bih + (size_t)l * G4, bhh + (size_t)l * G4, nullptr,
                    cst, h_o, ysw);
            }
        }
    }

    // out = sigmoid(ys @ ow.T + ob)  [262144, 88]
    gemm_bias_kernel<true><<<dim3((OUTN + 63) / 64, (BB * TT) / 64), 256>>>(
        ys, ow, ob, out, BB * TT, OUTN, HH, OUTN);
}

// round 5
// speedup vs baseline: 1.9987x; 1.9987x over previous
#include <cuda_runtime.h>
#include <math.h>
#include <stdint.h>

#define BB     4096
#define LATENT 128
#define HH     256
#define G4     1024   // 4*HH
#define OUTN   88
#define TT     64
#define LL     5

// ---------------- static device scratch (no allocations allowed) -------------
__device__ float g_h[LL * 2 * BB * HH];
__device__ float g_c[LL * BB * HH];
__device__ float g_xp[BB * HH];
__device__ float g_gx0[BB * G4];
__device__ float g_ys[BB * TT * HH];

// ---------------------------------------------------------------------------
__global__ void zero_kernel(float* __restrict__ p, int n) {
    int i = blockIdx.x * blockDim.x + threadIdx.x;
    int stride = gridDim.x * blockDim.x;
    for (; i < n; i += stride) p[i] = 0.0f;
}

__device__ __forceinline__ float sigf(float x) { return 1.0f / (1.0f + __expf(-x)); }
__device__ __forceinline__ float tanh_fast(float x) {
    float t = __expf(-2.0f * fabsf(x));
    float r = (1.0f - t) / (1.0f + t);
    return copysignf(r, x);
}
// tf32 conversion: destination is a b32 register in PTX.
__device__ __forceinline__ uint32_t tf32r(float x) {
    uint32_t r;
    asm("cvt.rna.tf32.f32 %0, %1;" : "=r"(r) : "f"(x));
    return r;
}
__device__ __forceinline__ void mma8(float* d, const uint32_t* a, uint32_t b0, uint32_t b1) {
    asm volatile(
        "mma.sync.aligned.m16n8k8.row.col.f32.tf32.tf32.f32 "
        "{%0,%1,%2,%3},{%4,%5,%6,%7},{%8,%9},{%0,%1,%2,%3};"
        : "+f"(d[0]), "+f"(d[1]), "+f"(d[2]), "+f"(d[3])
        : "r"(a[0]), "r"(a[1]), "r"(a[2]), "r"(a[3]), "r"(b0), "r"(b1));
}

// ---------------------------------------------------------------------------
// Fused tf32 mma.sync LSTM cell.
// CTA tile: 64 batch x 256 gate-cols (4 gates x 64 units). 8 warps (2m x 4n),
// warp tile 32x64 via m16n8k8. K staged 16 at a time, reg-prefetch + 2 smem bufs.
// gates = A0@W0^T [+ A1@W1^T] (+bih) + bhh (+gx0), then LSTM nonlinearity.
// Gate pre-acts staged through smem (overlaps staging bufs) for coalesced epilogue.
// ---------------------------------------------------------------------------
#define KT       16
#define ASTRIDE  20            // 16 + 4 pad (words)
#define SM_A0F   0             // 64*20   = 1280 words
#define SM_B0F   1280          // 256*20  = 5120 words
#define SM_A1F   6400
#define SM_B1F   7680
#define GSTRIDE  258           // gate buffer row stride (floats)
#define SM_WORDS (64 * GSTRIDE)       // 16512 words = 66048 bytes (union w/ staging)
#define SM_BYTES  (SM_WORDS * 4)

__global__ __launch_bounds__(256, 2) void cell_mma_kernel(
    const float* __restrict__ A0, const float* __restrict__ W0,
    const float* __restrict__ A1, const float* __restrict__ W1,
    int nst, int half,
    const float* __restrict__ bih, const float* __restrict__ bhh,
    const float* __restrict__ gx0,
    float* __restrict__ c_state, float* __restrict__ h_out,
    float* __restrict__ ys)
{
    extern __shared__ uint32_t sm[];
    const int tid = threadIdx.x;
    const int wid = tid >> 5, lane = tid & 31;
    const int grp = lane >> 2, tig = lane & 3;
    const int wm = wid & 1, wn = wid >> 1;
    const int m0 = blockIdx.y * 64;
    const int n0 = blockIdx.x * 64;

    uint32_t* Asm[2] = { sm + SM_A0F, sm + SM_A1F };
    uint32_t* Bsm[2] = { sm + SM_B0F, sm + SM_B1F };

    float acc[2][8][4] = {};
    float4 pa;
    float4 pb[4];

    const int ar = tid >> 2, ac4 = (tid & 3) * 4;

    auto gload = [&](int s) {
        const float* A = A0; const float* W = W0; int kt = s * KT;
        if (s >= half) { A = A1; W = W1; kt = (s - half) * KT; }
        pa = *reinterpret_cast<const float4*>(A + (size_t)(m0 + ar) * HH + kt + ac4);
#pragma unroll
        for (int i = 0; i < 4; i++) {
            int idx = i * 256 + tid;
            int r = idx >> 2, c4 = (idx & 3) * 4;
            int wrow = (r >> 6) * HH + n0 + (r & 63);
            pb[i] = *reinterpret_cast<const float4*>(W + (size_t)wrow * HH + kt + c4);
        }
    };

    auto sstore = [&](int buf) {
        uint4 v;
        v.x = tf32r(pa.x); v.y = tf32r(pa.y); v.z = tf32r(pa.z); v.w = tf32r(pa.w);
        *reinterpret_cast<uint4*>(&Asm[buf][ar * ASTRIDE + ac4]) = v;
#pragma unroll
        for (int i = 0; i < 4; i++) {
            int idx = i * 256 + tid;
            int r = idx >> 2, c4 = (idx & 3) * 4;
            uint4 w;
            w.x = tf32r(pb[i].x); w.y = tf32r(pb[i].y);
            w.z = tf32r(pb[i].z); w.w = tf32r(pb[i].w);
            *reinterpret_cast<uint4*>(&Bsm[buf][r * ASTRIDE + c4]) = w;
        }
    };

    auto compute = [&](int buf) {
        const uint32_t* sa = Asm[buf];
        const uint32_t* sb = Bsm[buf];
#pragma unroll
        for (int kk = 0; kk < 2; kk++) {
            const int k0 = kk * 8;
            uint32_t af[2][4];
#pragma unroll
            for (int mt = 0; mt < 2; mt++) {
                int ra = wm * 32 + mt * 16 + grp;
                af[mt][0] = sa[ra * ASTRIDE + k0 + tig];
                af[mt][1] = sa[(ra + 8) * ASTRIDE + k0 + tig];
                af[mt][2] = sa[ra * ASTRIDE + k0 + tig + 4];
                af[mt][3] = sa[(ra + 8) * ASTRIDE + k0 + tig + 4];
            }
#pragma unroll
            for (int nt = 0; nt < 8; nt++) {
                int rb = wn * 64 + nt * 8 + grp;
                uint32_t b0 = sb[rb * ASTRIDE + k0 + tig];
                uint32_t b1 = sb[rb * ASTRIDE + k0 + tig + 4];
#pragma unroll
                for (int mt = 0; mt < 2; mt++)
                    mma8(acc[mt][nt], af[mt], b0, b1);
            }
        }
    };

    gload(0);
    for (int s = 0; s < nst; s++) {
        int buf = s & 1;
        sstore(buf);
        __syncthreads();
        if (s + 1 < nst) gload(s + 1);
        compute(buf);
        __syncthreads();
    }

    // ---- write gate pre-activations to smem (overlaps dead staging bufs) ----
    float* smf = reinterpret_cast<float*>(sm);
#pragma unroll
    for (int mt = 0; mt < 2; mt++) {
#pragma unroll
        for (int nt = 0; nt < 8; nt++) {
            int row = wm * 32 + mt * 16 + grp;
            int col = wn * 64 + nt * 8 + 2 * tig;
            *reinterpret_cast<float2*>(&smf[row * GSTRIDE + col]) =
                make_float2(acc[mt][nt][0], acc[mt][nt][1]);
            *reinterpret_cast<float2*>(&smf[(row + 8) * GSTRIDE + col]) =
                make_float2(acc[mt][nt][2], acc[mt][nt][3]);
        }
    }
    __syncthreads();

    // ---------------- epilogue: LSTM cell, coalesced global I/O -------------
    const int u = tid & 63;
    const int n = n0 + u;
    const int bloc0 = (tid >> 6) * 16;

    float bsum[4];
#pragma unroll
    for (int gg = 0; gg < 4; gg++) {
        float v = bhh[gg * HH + n];
        if (bih) v += bih[gg * HH + n];
        bsum[gg] = v;
    }

    for (int i = 0; i < 16; i++) {
        const int bl = bloc0 + i;
        const int gb = m0 + bl;
        float pre[4];
#pragma unroll
        for (int gg = 0; gg < 4; gg++)
            pre[gg] = smf[bl * GSTRIDE + gg * 64 + u] + bsum[gg];
        if (gx0) {
#pragma unroll
            for (int gg = 0; gg < 4; gg++)
                pre[gg] += gx0[(size_t)gb * G4 + gg * HH + n];
        }
        float co = c_state[(size_t)gb * HH + n];
        float iv = sigf(pre[0]);
        float fv = sigf(pre[1]);
        float gv = tanh_fast(pre[2]);
        float ov = sigf(pre[3]);
        float cn = fv * co + iv * gv;
        float hn = ov * tanh_fast(cn);
        c_state[(size_t)gb * HH + n] = cn;
        h_out[(size_t)gb * HH + n] = hn;
        if (ys) ys[(size_t)gb * (TT * HH) + n] = hn;
    }
}

// ---------------------------------------------------------------------------
// SIMT GEMM (small projections + output GEMM)
template <bool SIG>
__global__ __launch_bounds__(256) void gemm_bias_kernel(
    const float* __restrict__ A, const float* __restrict__ Wt,
    const float* __restrict__ bias, float* __restrict__ C,
    int M, int N, int K, int ldc)
{
    __shared__ float As[2][8][64];
    __shared__ float Bs[2][8][64];
    const int tid = threadIdx.x;
    const int tx = tid & 15, ty = tid >> 4;
    const int m0 = blockIdx.y * 64, n0 = blockIdx.x * 64;
    const int lr = tid >> 2, lc = (tid & 3) * 2;

    float acc[4][4] = {};

    auto load = [&](int tile, int buf) {
        int kt = tile * 8;
        float2 a2 = *reinterpret_cast<const float2*>(A + (size_t)(m0 + lr) * K + kt + lc);
        As[buf][lc][lr] = a2.x; As[buf][lc + 1][lr] = a2.y;
        float2 b2 = make_float2(0.0f, 0.0f);
        if (n0 + lr < N)
            b2 = *reinterpret_cast<const float2*>(Wt + (size_t)(n0 + lr) * K + kt + lc);
        Bs[buf][lc][lr] = b2.x; Bs[buf][lc + 1][lr] = b2.y;
    };

    const int ntiles = K >> 3;
    load(0, 0);
    __syncthreads();
    for (int tile = 0; tile < ntiles; ++tile) {
        int cur = tile & 1;
        if (tile + 1 < ntiles) load(tile + 1, cur ^ 1);
#pragma unroll
        for (int kk = 0; kk < 8; ++kk) {
            float4 av = *reinterpret_cast<const float4*>(&As[cur][kk][ty * 4]);
            float4 bv = *reinterpret_cast<const float4*>(&Bs[cur][kk][tx * 4]);
            float a[4] = {av.x, av.y, av.z, av.w};
            float bb[4] = {bv.x, bv.y, bv.z, bv.w};
#pragma unroll
            for (int mi = 0; mi < 4; ++mi)
#pragma unroll
                for (int ni = 0; ni < 4; ++ni)
                    acc[mi][ni] += a[mi] * bb[ni];
        }
        __syncthreads();
    }

#pragma unroll
    for (int mi = 0; mi < 4; ++mi) {
        int row = m0 + ty * 4 + mi;
#pragma unroll
        for (int ni = 0; ni < 4; ++ni) {
            int nn = n0 + tx * 4 + ni;
            if (nn < N) {
                float v = acc[mi][ni] + bias[nn];
                if (SIG) v = 1.0f / (1.0f + __expf(-v));
                C[(size_t)row * ldc + nn] = v;
            }
        }
    }
}

// ---------------------------------------------------------------------------
extern "C" void kernel_launch(void* const* d_in, const int* in_sizes, int n_in,
                              void* d_out, int out_size)
{
    const float* x   = (const float*)d_in[0];
    const float* lw  = (const float*)d_in[1];
    const float* lb  = (const float*)d_in[2];
    const float* wih = (const float*)d_in[3];
    const float* whh = (const float*)d_in[4];
    const float* bih = (const float*)d_in[5];
    const float* bhh = (const float*)d_in[6];
    const float* ow  = (const float*)d_in[7];
    const float* ob  = (const float*)d_in[8];
    float* out = (float*)d_out;

    float *hb, *cb, *xp, *gx0, *ys;
    cudaGetSymbolAddress((void**)&hb,  g_h);
    cudaGetSymbolAddress((void**)&cb,  g_c);
    cudaGetSymbolAddress((void**)&xp,  g_xp);
    cudaGetSymbolAddress((void**)&gx0, g_gx0);
    cudaGetSymbolAddress((void**)&ys,  g_ys);

    cudaFuncSetAttribute(cell_mma_kernel, cudaFuncAttributeMaxDynamicSharedMemorySize, SM_BYTES);

    zero_kernel<<<2048, 256>>>(hb, LL * 2 * BB * HH);
    zero_kernel<<<2048, 256>>>(cb, LL * BB * HH);

    // xp = x @ lw.T + lb
    gemm_bias_kernel<false><<<dim3(HH / 64, BB / 64), 256>>>(x, lw, lb, xp, BB, HH, LATENT, HH);
    // gx0 = xp @ wih[0].T + bih[0]  (constant over time)
    gemm_bias_kernel<false><<<dim3(G4 / 64, BB / 64), 256>>>(xp, wih, bih, gx0, BB, G4, HH, G4);

    const size_t layer_sz = (size_t)BB * HH;
    const dim3 cell_grid(4, 64);   // n-blocks x m-blocks
    for (int t = 0; t < TT; ++t) {
        for (int l = 0; l < LL; ++l) {
            float*       h_o    = hb + (size_t)(l * 2 + (t & 1)) * layer_sz;
            const float* h_prev = hb + (size_t)(l * 2 + ((t + 1) & 1)) * layer_sz;
            float*       cst    = cb + (size_t)l * layer_sz;
            float*       ysw    = (l == LL - 1) ? (ys + (size_t)t * HH) : nullptr;
            if (l == 0) {
                cell_mma_kernel<<<cell_grid, 256, SM_BYTES>>>(
                    h_prev, whh, nullptr, nullptr, 16, 16,
                    nullptr, bhh, gx0, cst, h_o, ysw);
            } else {
                const float* ain = hb + (size_t)((l - 1) * 2 + (t & 1)) * layer_sz;
                cell_mma_kernel<<<cell_grid, 256, SM_BYTES>>>(
                    ain, wih + (size_t)l * G4 * HH,
                    h_prev, whh + (size_t)l * G4 * HH, 32, 16,
                    bih + (size_t)l * G4, bhh + (size_t)l * G4, nullptr,
                    cst, h_o, ysw);
            }
        }
    }

    // out = sigmoid(ys @ ow.T + ob)
    gemm_bias_kernel<true><<<dim3((OUTN + 63) / 64, (BB * TT) / 64), 256>>>(
        ys, ow, ob, out, BB * TT, OUTN, HH, OUTN);
}

// round 6
// speedup vs baseline: 2.4316x; 1.2166x over previous
#include <cuda_runtime.h>
#include <math.h>
#include <stdint.h>

#define BB     4096
#define LATENT 128
#define HH     256
#define G4     1024   // 4*HH
#define OUTN   88
#define TT     64
#define LL     5

// ---------------- static device scratch (no allocations allowed) -------------
__device__ float g_h[LL * 2 * BB * HH];
__device__ float g_c[LL * BB * HH];
__device__ float g_xp[BB * HH];
__device__ float g_gx0[BB * G4];
__device__ float g_ys[BB * TT * HH];

// ---------------------------------------------------------------------------
__global__ void zero_kernel(float* __restrict__ p, int n) {
    int i = blockIdx.x * blockDim.x + threadIdx.x;
    int stride = gridDim.x * blockDim.x;
    for (; i < n; i += stride) p[i] = 0.0f;
}

__device__ __forceinline__ float sigf(float x) { return 1.0f / (1.0f + __expf(-x)); }
__device__ __forceinline__ float tanh_fast(float x) {
    float t = __expf(-2.0f * fabsf(x));
    float r = (1.0f - t) / (1.0f + t);
    return copysignf(r, x);
}
__device__ __forceinline__ void mma8(float* d, const uint32_t* a, uint32_t b0, uint32_t b1) {
    asm volatile(
        "mma.sync.aligned.m16n8k8.row.col.f32.tf32.tf32.f32 "
        "{%0,%1,%2,%3},{%4,%5,%6,%7},{%8,%9},{%0,%1,%2,%3};"
        : "+f"(d[0]), "+f"(d[1]), "+f"(d[2]), "+f"(d[3])
        : "r"(a[0]), "r"(a[1]), "r"(a[2]), "r"(a[3]), "r"(b0), "r"(b1));
}
__device__ __forceinline__ uint32_t smem_u32(const void* p) {
    uint32_t a;
    asm("{ .reg .u64 t; cvta.to.shared.u64 t, %1; cvt.u32.u64 %0, t; }" : "=r"(a) : "l"(p));
    return a;
}
__device__ __forceinline__ void cpasync16(uint32_t dst, const void* src) {
    asm volatile("cp.async.cg.shared.global [%0], [%1], 16;" :: "r"(dst), "l"(src) : "memory");
}
#define CP_COMMIT() asm volatile("cp.async.commit_group;" ::: "memory")
#define CP_WAIT2()  asm volatile("cp.async.wait_group 2;" ::: "memory")

// ---------------------------------------------------------------------------
// Fused tf32 mma.sync LSTM cell, cp.async 3-stage pipeline.
// CTA tile: 64 batch x 256 gate-cols (4 gates x 64 units). 8 warps (2m x 4n),
// warp tile 32x64 via m16n8k8. K staged 16-wide; fp32 bits fed to tf32 mma
// (hardware truncation, no explicit cvt).
// ---------------------------------------------------------------------------
#define KT          16
#define ASTRIDE     20                 // 16 + 4 pad (words)
#define STAGE_WORDS 6400               // (64 + 256) * 20
#define AOFFW       0                  // A rows 0..63
#define BOFFW       1280               // B rows 0..255
#define NSTAGE      3
#define GSTRIDE     258                // epilogue gate buffer row stride (floats)
#define SM_WORDS    (NSTAGE * STAGE_WORDS)    // 19200 words = 76800 B (> 64*258=16512)
#define SM_BYTES    (SM_WORDS * 4)

__global__ __launch_bounds__(256, 2) void cell_mma_kernel(
    const float* __restrict__ A0, const float* __restrict__ W0,
    const float* __restrict__ A1, const float* __restrict__ W1,
    int nst, int half,
    const float* __restrict__ bih, const float* __restrict__ bhh,
    const float* __restrict__ gx0,
    float* __restrict__ c_state, float* __restrict__ h_out,
    float* __restrict__ ys)
{
    extern __shared__ uint32_t sm[];
    const uint32_t sbase = smem_u32(sm);
    const int tid = threadIdx.x;
    const int wid = tid >> 5, lane = tid & 31;
    const int grp = lane >> 2, tig = lane & 3;
    const int wm = wid & 1, wn = wid >> 1;
    const int m0 = blockIdx.y * 64;
    const int n0 = blockIdx.x * 64;

    float acc[2][8][4] = {};

    // per-thread load assignment (1 A chunk + 4 B chunks of 16B per stage)
    const int a_r = tid >> 2, a_c = (tid & 3) * 4;

    auto load_stage = [&](int s, int buf) {
        const float* A = A0; const float* W = W0; int kt = s * KT;
        if (s >= half) { A = A1; W = W1; kt = (s - half) * KT; }
        const uint32_t base = sbase + (uint32_t)buf * (STAGE_WORDS * 4);
        cpasync16(base + (AOFFW + a_r * ASTRIDE + a_c) * 4,
                  A + (size_t)(m0 + a_r) * HH + kt + a_c);
#pragma unroll
        for (int i = 0; i < 4; i++) {
            int idx = i * 256 + tid;
            int r = idx >> 2, c4 = (idx & 3) * 4;
            int wrow = (r >> 6) * HH + n0 + (r & 63);
            cpasync16(base + (BOFFW + r * ASTRIDE + c4) * 4,
                      W + (size_t)wrow * HH + kt + c4);
        }
    };

    auto compute = [&](int buf) {
        const uint32_t* sa = sm + buf * STAGE_WORDS + AOFFW;
        const uint32_t* sb = sm + buf * STAGE_WORDS + BOFFW;
#pragma unroll
        for (int kk = 0; kk < 2; kk++) {
            const int k0 = kk * 8;
            uint32_t af[2][4];
#pragma unroll
            for (int mt = 0; mt < 2; mt++) {
                int ra = wm * 32 + mt * 16 + grp;
                af[mt][0] = sa[ra * ASTRIDE + k0 + tig];
                af[mt][1] = sa[(ra + 8) * ASTRIDE + k0 + tig];
                af[mt][2] = sa[ra * ASTRIDE + k0 + tig + 4];
                af[mt][3] = sa[(ra + 8) * ASTRIDE + k0 + tig + 4];
            }
#pragma unroll
            for (int nt = 0; nt < 8; nt++) {
                int rb = wn * 64 + nt * 8 + grp;
                uint32_t b0 = sb[rb * ASTRIDE + k0 + tig];
                uint32_t b1 = sb[rb * ASTRIDE + k0 + tig + 4];
#pragma unroll
                for (int mt = 0; mt < 2; mt++)
                    mma8(acc[mt][nt], af[mt], b0, b1);
            }
        }
    };

    // ---- prologue: fill the 3-deep pipe ----
#pragma unroll
    for (int p = 0; p < NSTAGE; p++) {
        load_stage(p, p);            // nst >= 3 always (16 or 32)
        CP_COMMIT();
    }

    for (int s = 0; s < nst; s++) {
        CP_WAIT2();
        __syncthreads();
        int buf = s % NSTAGE;
        compute(buf);
        __syncthreads();
        if (s + NSTAGE < nst) load_stage(s + NSTAGE, buf);
        CP_COMMIT();                 // empty groups at the tail keep accounting uniform
    }

    // ---- write gate pre-activations to smem (staging bufs are dead now) ----
    float* smf = reinterpret_cast<float*>(sm);
#pragma unroll
    for (int mt = 0; mt < 2; mt++) {
#pragma unroll
        for (int nt = 0; nt < 8; nt++) {
            int row = wm * 32 + mt * 16 + grp;
            int col = wn * 64 + nt * 8 + 2 * tig;
            *reinterpret_cast<float2*>(&smf[row * GSTRIDE + col]) =
                make_float2(acc[mt][nt][0], acc[mt][nt][1]);
            *reinterpret_cast<float2*>(&smf[(row + 8) * GSTRIDE + col]) =
                make_float2(acc[mt][nt][2], acc[mt][nt][3]);
        }
    }
    __syncthreads();

    // ---------------- epilogue: LSTM cell, coalesced global I/O -------------
    const int u = tid & 63;
    const int n = n0 + u;
    const int bloc0 = (tid >> 6) * 16;

    float bsum[4];
#pragma unroll
    for (int gg = 0; gg < 4; gg++) {
        float v = bhh[gg * HH + n];
        if (bih) v += bih[gg * HH + n];
        bsum[gg] = v;
    }

    for (int i = 0; i < 16; i++) {
        const int bl = bloc0 + i;
        const int gb = m0 + bl;
        float pre[4];
#pragma unroll
        for (int gg = 0; gg < 4; gg++)
            pre[gg] = smf[bl * GSTRIDE + gg * 64 + u] + bsum[gg];
        if (gx0) {
#pragma unroll
            for (int gg = 0; gg < 4; gg++)
                pre[gg] += gx0[(size_t)gb * G4 + gg * HH + n];
        }
        float co = c_state[(size_t)gb * HH + n];
        float iv = sigf(pre[0]);
        float fv = sigf(pre[1]);
        float gv = tanh_fast(pre[2]);
        float ov = sigf(pre[3]);
        float cn = fv * co + iv * gv;
        float hn = ov * tanh_fast(cn);
        c_state[(size_t)gb * HH + n] = cn;
        h_out[(size_t)gb * HH + n] = hn;
        if (ys) ys[(size_t)gb * (TT * HH) + n] = hn;
    }
}

// ---------------------------------------------------------------------------
// SIMT GEMM (small projections + output GEMM)
template <bool SIG>
__global__ __launch_bounds__(256) void gemm_bias_kernel(
    const float* __restrict__ A, const float* __restrict__ Wt,
    const float* __restrict__ bias, float* __restrict__ C,
    int M, int N, int K, int ldc)
{
    __shared__ float As[2][8][64];
    __shared__ float Bs[2][8][64];
    const int tid = threadIdx.x;
    const int tx = tid & 15, ty = tid >> 4;
    const int m0 = blockIdx.y * 64, n0 = blockIdx.x * 64;
    const int lr = tid >> 2, lc = (tid & 3) * 2;

    float acc[4][4] = {};

    auto load = [&](int tile, int buf) {
        int kt = tile * 8;
        float2 a2 = *reinterpret_cast<const float2*>(A + (size_t)(m0 + lr) * K + kt + lc);
        As[buf][lc][lr] = a2.x; As[buf][lc + 1][lr] = a2.y;
        float2 b2 = make_float2(0.0f, 0.0f);
        if (n0 + lr < N)
            b2 = *reinterpret_cast<const float2*>(Wt + (size_t)(n0 + lr) * K + kt + lc);
        Bs[buf][lc][lr] = b2.x; Bs[buf][lc + 1][lr] = b2.y;
    };

    const int ntiles = K >> 3;
    load(0, 0);
    __syncthreads();
    for (int tile = 0; tile < ntiles; ++tile) {
        int cur = tile & 1;
        if (tile + 1 < ntiles) load(tile + 1, cur ^ 1);
#pragma unroll
        for (int kk = 0; kk < 8; ++kk) {
            float4 av = *reinterpret_cast<const float4*>(&As[cur][kk][ty * 4]);
            float4 bv = *reinterpret_cast<const float4*>(&Bs[cur][kk][tx * 4]);
            float a[4] = {av.x, av.y, av.z, av.w};
            float bb[4] = {bv.x, bv.y, bv.z, bv.w};
#pragma unroll
            for (int mi = 0; mi < 4; ++mi)
#pragma unroll
                for (int ni = 0; ni < 4; ++ni)
                    acc[mi][ni] += a[mi] * bb[ni];
        }
        __syncthreads();
    }

#pragma unroll
    for (int mi = 0; mi < 4; ++mi) {
        int row = m0 + ty * 4 + mi;
#pragma unroll
        for (int ni = 0; ni < 4; ++ni) {
            int nn = n0 + tx * 4 + ni;
            if (nn < N) {
                float v = acc[mi][ni] + bias[nn];
                if (SIG) v = 1.0f / (1.0f + __expf(-v));
                C[(size_t)row * ldc + nn] = v;
            }
        }
    }
}

// ---------------------------------------------------------------------------
extern "C" void kernel_launch(void* const* d_in, const int* in_sizes, int n_in,
                              void* d_out, int out_size)
{
    const float* x   = (const float*)d_in[0];
    const float* lw  = (const float*)d_in[1];
    const float* lb  = (const float*)d_in[2];
    const float* wih = (const float*)d_in[3];
    const float* whh = (const float*)d_in[4];
    const float* bih = (const float*)d_in[5];
    const float* bhh = (const float*)d_in[6];
    const float* ow  = (const float*)d_in[7];
    const float* ob  = (const float*)d_in[8];
    float* out = (float*)d_out;

    float *hb, *cb, *xp, *gx0, *ys;
    cudaGetSymbolAddress((void**)&hb,  g_h);
    cudaGetSymbolAddress((void**)&cb,  g_c);
    cudaGetSymbolAddress((void**)&xp,  g_xp);
    cudaGetSymbolAddress((void**)&gx0, g_gx0);
    cudaGetSymbolAddress((void**)&ys,  g_ys);

    cudaFuncSetAttribute(cell_mma_kernel, cudaFuncAttributeMaxDynamicSharedMemorySize, SM_BYTES);

    zero_kernel<<<2048, 256>>>(hb, LL * 2 * BB * HH);
    zero_kernel<<<2048, 256>>>(cb, LL * BB * HH);

    // xp = x @ lw.T + lb
    gemm_bias_kernel<false><<<dim3(HH / 64, BB / 64), 256>>>(x, lw, lb, xp, BB, HH, LATENT, HH);
    // gx0 = xp @ wih[0].T + bih[0]  (constant over time)
    gemm_bias_kernel<false><<<dim3(G4 / 64, BB / 64), 256>>>(xp, wih, bih, gx0, BB, G4, HH, G4);

    const size_t layer_sz = (size_t)BB * HH;
    const dim3 cell_grid(4, 64);   // n-blocks x m-blocks
    for (int t = 0; t < TT; ++t) {
        for (int l = 0; l < LL; ++l) {
            float*       h_o    = hb + (size_t)(l * 2 + (t & 1)) * layer_sz;
            const float* h_prev = hb + (size_t)(l * 2 + ((t + 1) & 1)) * layer_sz;
            float*       cst    = cb + (size_t)l * layer_sz;
            float*       ysw    = (l == LL - 1) ? (ys + (size_t)t * HH) : nullptr;
            if (l == 0) {
                cell_mma_kernel<<<cell_grid, 256, SM_BYTES>>>(
                    h_prev, whh, nullptr, nullptr, 16, 16,
                    nullptr, bhh, gx0, cst, h_o, ysw);
            } else {
                const float* ain = hb + (size_t)((l - 1) * 2 + (t & 1)) * layer_sz;
                cell_mma_kernel<<<cell_grid, 256, SM_BYTES>>>(
                    ain, wih + (size_t)l * G4 * HH,
                    h_prev, whh + (size_t)l * G4 * HH, 32, 16,
                    bih + (size_t)l * G4, bhh + (size_t)l * G4, nullptr,
                    cst, h_o, ysw);
            }
        }
    }

    // out = sigmoid(ys @ ow.T + ob)
    gemm_bias_kernel<true><<<dim3((OUTN + 63) / 64, (BB * TT) / 64), 256>>>(
        ys, ow, ob, out, BB * TT, OUTN, HH, OUTN);
}

// round 8
// speedup vs baseline: 3.0587x; 1.2579x over previous
#include <cuda_runtime.h>
#include <math.h>
#include <stdint.h>

#define BB     4096
#define LATENT 128
#define HH     256
#define G4     1024   // 4*HH
#define OUTN   88
#define TT     64
#define LL     5

// ---------------- static device scratch (no allocations allowed) -------------
__device__ float g_h[LL * 2 * BB * HH];   // per-layer h, parity double-buffered
__device__ float g_c[LL * BB * HH];
__device__ float g_xp[BB * HH];
__device__ float g_gx0[BB * G4];          // layer-0 input gates (const over t)
__device__ float g_ys[BB * TT * HH];      // [B][T][H]

// ---------------------------------------------------------------------------
__global__ void zero_kernel(float* __restrict__ p, int n) {
    int i = blockIdx.x * blockDim.x + threadIdx.x;
    int stride = gridDim.x * blockDim.x;
    for (; i < n; i += stride) p[i] = 0.0f;
}

__device__ __forceinline__ float sigf(float x) { return 1.0f / (1.0f + __expf(-x)); }
__device__ __forceinline__ float tanh_fast(float x) {
    float t = __expf(-2.0f * fabsf(x));
    float r = (1.0f - t) / (1.0f + t);
    return copysignf(r, x);
}
__device__ __forceinline__ void mma8(float* d, const uint32_t* a, uint32_t b0, uint32_t b1) {
    asm volatile(
        "mma.sync.aligned.m16n8k8.row.col.f32.tf32.tf32.f32 "
        "{%0,%1,%2,%3},{%4,%5,%6,%7},{%8,%9},{%0,%1,%2,%3};"
        : "+f"(d[0]), "+f"(d[1]), "+f"(d[2]), "+f"(d[3])
        : "r"(a[0]), "r"(a[1]), "r"(a[2]), "r"(a[3]), "r"(b0), "r"(b1));
}
__device__ __forceinline__ uint32_t smem_u32(const void* p) {
    uint32_t a;
    asm("{ .reg .u64 t; cvta.to.shared.u64 t, %1; cvt.u32.u64 %0, t; }" : "=r"(a) : "l"(p));
    return a;
}
__device__ __forceinline__ void cpasync16(uint32_t dst, const void* src) {
    asm volatile("cp.async.cg.shared.global [%0], [%1], 16;" :: "r"(dst), "l"(src) : "memory");
}
#define CP_COMMIT() asm volatile("cp.async.commit_group;" ::: "memory")
#define CP_WAIT3()  asm volatile("cp.async.wait_group 3;" ::: "memory")

// ---------------------------------------------------------------------------
// Wavefront-fused tf32 mma.sync LSTM cell.
// One launch per diagonal k = l + t; blockIdx.z enumerates the independent
// cells on the diagonal. CTA tile: 64 batch x 256 gate-cols (4 gates x 64
// units); 8 warps (2m x 4n), warp tile 32x64 via m16n8k8; cp.async 4-stage
// pipeline; fp32 bits fed to tf32 mma (hardware truncation).
// ---------------------------------------------------------------------------
#define KT          16
#define ASTRIDE     20                 // 16 + 4 pad (words)
#define STAGE_WORDS 6400               // (64 + 256) * 20
#define AOFFW       0
#define BOFFW       1280
#define NSTAGE      4
#define GSTRIDE     258                // epilogue gate buffer row stride (floats)
#define SM_WORDS    (NSTAGE * STAGE_WORDS)    // 25600 words = 102400 B
#define SM_BYTES    (SM_WORDS * 4)

__global__ __launch_bounds__(256, 2) void cell_diag_kernel(
    int kdiag, int lmin,
    const float* __restrict__ wih, const float* __restrict__ whh,
    const float* __restrict__ bih_g, const float* __restrict__ bhh_g)
{
    extern __shared__ uint32_t sm[];
    const uint32_t sbase = smem_u32(sm);
    const int tid = threadIdx.x;
    const int wid = tid >> 5, lane = tid & 31;
    const int grp = lane >> 2, tig = lane & 3;
    const int wm = wid & 1, wn = wid >> 1;
    const int m0 = blockIdx.y * 64;
    const int n0 = blockIdx.x * 64;

    // ---- derive this cell's operands from (kdiag, z) ----
    const int l = lmin + blockIdx.z;
    const int t = kdiag - l;
    const size_t lsz = (size_t)BB * HH;
    const float* h_prev = g_h + (size_t)(l * 2 + ((t + 1) & 1)) * lsz;
    float*       h_o    = g_h + (size_t)(l * 2 + (t & 1)) * lsz;
    float*       cst    = g_c + (size_t)l * lsz;
    float*       ys     = (l == LL - 1) ? (g_ys + (size_t)t * HH) : nullptr;

    const float *A0, *W0, *A1, *W1, *bih, *gx0;
    int nst;
    const float* bhh = bhh_g + l * G4;
    if (l == 0) {
        A0 = h_prev; W0 = whh; A1 = nullptr; W1 = nullptr;
        nst = 16; bih = nullptr; gx0 = g_gx0;
    } else {
        A0 = g_h + (size_t)((l - 1) * 2 + (t & 1)) * lsz;
        W0 = wih + (size_t)l * G4 * HH;
        A1 = h_prev;
        W1 = whh + (size_t)l * G4 * HH;
        nst = 32; bih = bih_g + l * G4; gx0 = nullptr;
    }
    const int half = 16;

    float acc[2][8][4] = {};

    const int a_r = tid >> 2, a_c = (tid & 3) * 4;

    auto load_stage = [&](int s, int buf) {
        const float* A = A0; const float* W = W0; int kt = s * KT;
        if (s >= half) { A = A1; W = W1; kt = (s - half) * KT; }
        const uint32_t base = sbase + (uint32_t)buf * (STAGE_WORDS * 4);
        cpasync16(base + (AOFFW + a_r * ASTRIDE + a_c) * 4,
                  A + (size_t)(m0 + a_r) * HH + kt + a_c);
#pragma unroll
        for (int i = 0; i < 4; i++) {
            int idx = i * 256 + tid;
            int r = idx >> 2, c4 = (idx & 3) * 4;
            int wrow = (r >> 6) * HH + n0 + (r & 63);
            cpasync16(base + (BOFFW + r * ASTRIDE + c4) * 4,
                      W + (size_t)wrow * HH + kt + c4);
        }
    };

    auto compute = [&](int buf) {
        const uint32_t* sa = sm + buf * STAGE_WORDS + AOFFW;
        const uint32_t* sb = sm + buf * STAGE_WORDS + BOFFW;
#pragma unroll
        for (int kk = 0; kk < 2; kk++) {
            const int k0 = kk * 8;
            uint32_t af[2][4];
#pragma unroll
            for (int mt = 0; mt < 2; mt++) {
                int ra = wm * 32 + mt * 16 + grp;
                af[mt][0] = sa[ra * ASTRIDE + k0 + tig];
                af[mt][1] = sa[(ra + 8) * ASTRIDE + k0 + tig];
                af[mt][2] = sa[ra * ASTRIDE + k0 + tig + 4];
                af[mt][3] = sa[(ra + 8) * ASTRIDE + k0 + tig + 4];
            }
#pragma unroll
            for (int nt = 0; nt < 8; nt++) {
                int rb = wn * 64 + nt * 8 + grp;
                uint32_t b0 = sb[rb * ASTRIDE + k0 + tig];
                uint32_t b1 = sb[rb * ASTRIDE + k0 + tig + 4];
#pragma unroll
                for (int mt = 0; mt < 2; mt++)
                    mma8(acc[mt][nt], af[mt], b0, b1);
            }
        }
    };

    // ---- prologue: fill the 4-deep pipe (nst >= 16 always) ----
#pragma unroll
    for (int p = 0; p < NSTAGE; p++) {
        load_stage(p, p);
        CP_COMMIT();
    }

    for (int s = 0; s < nst; s++) {
        CP_WAIT3();
        __syncthreads();
        int buf = s & (NSTAGE - 1);
        compute(buf);
        __syncthreads();
        if (s + NSTAGE < nst) load_stage(s + NSTAGE, buf);
        CP_COMMIT();                 // empty tail groups keep accounting uniform
    }

    // ---- write gate pre-activations to smem (staging bufs dead now) ----
    float* smf = reinterpret_cast<float*>(sm);
#pragma unroll
    for (int mt = 0; mt < 2; mt++) {
#pragma unroll
        for (int nt = 0; nt < 8; nt++) {
            int row = wm * 32 + mt * 16 + grp;
            int col = wn * 64 + nt * 8 + 2 * tig;
            *reinterpret_cast<float2*>(&smf[row * GSTRIDE + col]) =
                make_float2(acc[mt][nt][0], acc[mt][nt][1]);
            *reinterpret_cast<float2*>(&smf[(row + 8) * GSTRIDE + col]) =
                make_float2(acc[mt][nt][2], acc[mt][nt][3]);
        }
    }
    __syncthreads();

    // ---------------- epilogue: LSTM cell, coalesced global I/O -------------
    const int u = tid & 63;
    const int n = n0 + u;
    const int bloc0 = (tid >> 6) * 16;

    float bsum[4];
#pragma unroll
    for (int gg = 0; gg < 4; gg++) {
        float v = bhh[gg * HH + n];
        if (bih) v += bih[gg * HH + n];
        bsum[gg] = v;
    }

    for (int i = 0; i < 16; i++) {
        const int bl = bloc0 + i;
        const int gb = m0 + bl;
        float pre[4];
#pragma unroll
        for (int gg = 0; gg < 4; gg++)
            pre[gg] = smf[bl * GSTRIDE + gg * 64 + u] + bsum[gg];
        if (gx0) {
#pragma unroll
            for (int gg = 0; gg < 4; gg++)
                pre[gg] += gx0[(size_t)gb * G4 + gg * HH + n];
        }
        float co = cst[(size_t)gb * HH + n];
        float iv = sigf(pre[0]);
        float fv = sigf(pre[1]);
        float gv = tanh_fast(pre[2]);
        float ov = sigf(pre[3]);
        float cn = fv * co + iv * gv;
        float hn = ov * tanh_fast(cn);
        cst[(size_t)gb * HH + n] = cn;
        h_o[(size_t)gb * HH + n] = hn;
        if (ys) ys[(size_t)gb * (TT * HH) + n] = hn;
    }
}

// ---------------------------------------------------------------------------
// SIMT GEMM (small projections + output GEMM)
template <bool SIG>
__global__ __launch_bounds__(256) void gemm_bias_kernel(
    const float* __restrict__ A, const float* __restrict__ Wt,
    const float* __restrict__ bias, float* __restrict__ C,
    int M, int N, int K, int ldc)
{
    __shared__ float As[2][8][64];
    __shared__ float Bs[2][8][64];
    const int tid = threadIdx.x;
    const int tx = tid & 15, ty = tid >> 4;
    const int m0 = blockIdx.y * 64, n0 = blockIdx.x * 64;
    const int lr = tid >> 2, lc = (tid & 3) * 2;

    float acc[4][4] = {};

    auto load = [&](int tile, int buf) {
        int kt = tile * 8;
        float2 a2 = *reinterpret_cast<const float2*>(A + (size_t)(m0 + lr) * K + kt + lc);
        As[buf][lc][lr] = a2.x; As[buf][lc + 1][lr] = a2.y;
        float2 b2 = make_float2(0.0f, 0.0f);
        if (n0 + lr < N)
            b2 = *reinterpret_cast<const float2*>(Wt + (size_t)(n0 + lr) * K + kt + lc);
        Bs[buf][lc][lr] = b2.x; Bs[buf][lc + 1][lr] = b2.y;
    };

    const int ntiles = K >> 3;
    load(0, 0);
    __syncthreads();
    for (int tile = 0; tile < ntiles; ++tile) {
        int cur = tile & 1;
        if (tile + 1 < ntiles) load(tile + 1, cur ^ 1);
#pragma unroll
        for (int kk = 0; kk < 8; ++kk) {
            float4 av = *reinterpret_cast<const float4*>(&As[cur][kk][ty * 4]);
            float4 bv = *reinterpret_cast<const float4*>(&Bs[cur][kk][tx * 4]);
            float a[4] = {av.x, av.y, av.z, av.w};
            float bb[4] = {bv.x, bv.y, bv.z, bv.w};
#pragma unroll
            for (int mi = 0; mi < 4; ++mi)
#pragma unroll
                for (int ni = 0; ni < 4; ++ni)
                    acc[mi][ni] += a[mi] * bb[ni];
        }
        __syncthreads();
    }

#pragma unroll
    for (int mi = 0; mi < 4; ++mi) {
        int row = m0 + ty * 4 + mi;
#pragma unroll
        for (int ni = 0; ni < 4; ++ni) {
            int nn = n0 + tx * 4 + ni;
            if (nn < N) {
                float v = acc[mi][ni] + bias[nn];
                if (SIG) v = 1.0f / (1.0f + __expf(-v));
                C[(size_t)row * ldc + nn] = v;
            }
        }
    }
}

// ---------------------------------------------------------------------------
extern "C" void kernel_launch(void* const* d_in, const int* in_sizes, int n_in,
                              void* d_out, int out_size)
{
    const float* x   = (const float*)d_in[0];
    const float* lw  = (const float*)d_in[1];
    const float* lb  = (const float*)d_in[2];
    const float* wih = (const float*)d_in[3];
    const float* whh = (const float*)d_in[4];
    const float* bih = (const float*)d_in[5];
    const float* bhh = (const float*)d_in[6];
    const float* ow  = (const float*)d_in[7];
    const float* ob  = (const float*)d_in[8];
    float* out = (float*)d_out;

    float *hb, *cb, *xp, *gx0, *ys;
    cudaGetSymbolAddress((void**)&hb,  g_h);
    cudaGetSymbolAddress((void**)&cb,  g_c);
    cudaGetSymbolAddress((void**)&xp,  g_xp);
    cudaGetSymbolAddress((void**)&gx0, g_gx0);
    cudaGetSymbolAddress((void**)&ys,  g_ys);

    cudaFuncSetAttribute(cell_diag_kernel, cudaFuncAttributeMaxDynamicSharedMemorySize, SM_BYTES);

    zero_kernel<<<2048, 256>>>(hb, LL * 2 * BB * HH);
    zero_kernel<<<2048, 256>>>(cb, LL * BB * HH);

    // xp = x @ lw.T + lb
    gemm_bias_kernel<false><<<dim3(HH / 64, BB / 64), 256>>>(x, lw, lb, xp, BB, HH, LATENT, HH);
    // gx0 = xp @ wih[0].T + bih[0]  (constant over time)
    gemm_bias_kernel<false><<<dim3(G4 / 64, BB / 64), 256>>>(xp, wih, bih, gx0, BB, G4, HH, G4);

    // ---- wavefront over diagonals k = l + t ----
    for (int k = 0; k < TT + LL - 1; ++k) {
        int lmin = k - (TT - 1); if (lmin < 0) lmin = 0;
        int lmax = k;            if (lmax > LL - 1) lmax = LL - 1;
        dim3 grid(4, 64, (unsigned)(lmax - lmin + 1));
        cell_diag_kernel<<<grid, 256, SM_BYTES>>>(k, lmin, wih, whh, bih, bhh);
    }

    // out = sigmoid(ys @ ow.T + ob)
    gemm_bias_kernel<true><<<dim3((OUTN + 63) / 64, (BB * TT) / 64), 256>>>(
        ys, ow, ob, out, BB * TT, OUTN, HH, OUTN);
}

// round 10
// speedup vs baseline: 4.4283x; 1.4478x over previous
#include <cuda_runtime.h>
#include <cuda_bf16.h>
#include <math.h>
#include <stdint.h>

#define BB     4096
#define LATENT 128
#define HH     256
#define G4     1024   // 4*HH
#define OUTN   88
#define TT     64
#define LL     5

// ---------------- static device scratch (no allocations allowed) -------------
__device__ float    g_c[LL * BB * HH];
__device__ float    g_xp[BB * HH];
__device__ float    g_gx0[BB * G4];              // layer-0 input gates (const over t)
__device__ float    g_ys[BB * TT * HH];          // [B][T][H] fp32
__device__ uint32_t g_hb32[LL * 2 * BB * HH / 2];   // h state, bf16 pairs, parity buffered
__device__ uint32_t g_wib32[LL * G4 * HH / 2];      // wih in bf16 pairs
__device__ uint32_t g_whb32[LL * G4 * HH / 2];      // whh in bf16 pairs

// ---------------------------------------------------------------------------
__global__ void zero_kernel(float* __restrict__ p, int n) {
    int i = blockIdx.x * blockDim.x + threadIdx.x;
    int stride = gridDim.x * blockDim.x;
    for (; i < n; i += stride) p[i] = 0.0f;
}

// fp32 -> packed bf16x2 conversion (n2 = number of OUTPUT words)
__global__ void f2bf_kernel(const float* __restrict__ in, uint32_t* __restrict__ out, int n2) {
    int i = blockIdx.x * blockDim.x + threadIdx.x;
    int stride = gridDim.x * blockDim.x;
    for (; i < n2; i += stride) {
        uint32_t lo = (uint32_t)__bfloat16_as_ushort(__float2bfloat16_rn(in[2 * i]));
        uint32_t hi = (uint32_t)__bfloat16_as_ushort(__float2bfloat16_rn(in[2 * i + 1]));
        out[i] = lo | (hi << 16);
    }
}

__device__ __forceinline__ float sigf(float x) { return 1.0f / (1.0f + __expf(-x)); }
__device__ __forceinline__ float tanh_fast(float x) {
    float t = __expf(-2.0f * fabsf(x));
    float r = (1.0f - t) / (1.0f + t);
    return copysignf(r, x);
}
__device__ __forceinline__ void mma16(float* d, const uint32_t* a, uint32_t b0, uint32_t b1) {
    asm volatile(
        "mma.sync.aligned.m16n8k16.row.col.f32.bf16.bf16.f32 "
        "{%0,%1,%2,%3},{%4,%5,%6,%7},{%8,%9},{%0,%1,%2,%3};"
        : "+f"(d[0]), "+f"(d[1]), "+f"(d[2]), "+f"(d[3])
        : "r"(a[0]), "r"(a[1]), "r"(a[2]), "r"(a[3]), "r"(b0), "r"(b1));
}
__device__ __forceinline__ uint32_t smem_u32(const void* p) {
    uint32_t a;
    asm("{ .reg .u64 t; cvta.to.shared.u64 t, %1; cvt.u32.u64 %0, t; }" : "=r"(a) : "l"(p));
    return a;
}
__device__ __forceinline__ void cpasync16(uint32_t dst, const void* src) {
    asm volatile("cp.async.cg.shared.global [%0], [%1], 16;" :: "r"(dst), "l"(src) : "memory");
}
#define CP_COMMIT() asm volatile("cp.async.commit_group;" ::: "memory")
#define CP_WAIT3()  asm volatile("cp.async.wait_group 3;" ::: "memory")

// ---------------------------------------------------------------------------
// Wavefront-fused bf16 mma.sync LSTM cell.
// One launch per diagonal k = l + t; blockIdx.z enumerates the independent
// cells. CTA tile: 128 batch x 256 gate-cols (4 gates x 64 units); 512 threads,
// 16 warps (4m x 4n), warp tile 32x64 via m16n8k16; cp.async 4-stage pipeline,
// K staged 32 bf16 per stage. Accumulation + nonlinearity in fp32.
// ---------------------------------------------------------------------------
#define KT          32                 // bf16 k-elems per stage
#define RSW         20                 // row stride in 32-bit words (32 bf16 + 8 pad)
#define AROWS       128
#define BROWS       256
#define STAGE_WORDS ((AROWS + BROWS) * RSW)   // 7680 words = 30720 B
#define AOFFW       0
#define BOFFW       (AROWS * RSW)      // 2560
#define NSTAGE      4
#define GSTRIDE     258                // epilogue gate buffer row stride (floats)
#define SM_WORDS    (AROWS * GSTRIDE)  // 33024 words = 132096 B (> 4*7680=30720)
#define SM_BYTES    (SM_WORDS * 4)

__global__ __launch_bounds__(512, 1) void cell_diag_kernel(
    int kdiag, int lmin,
    const float* __restrict__ bih_g, const float* __restrict__ bhh_g)
{
    extern __shared__ uint32_t sm[];
    const uint32_t sbase = smem_u32(sm);
    const int tid = threadIdx.x;
    const int wid = tid >> 5, lane = tid & 31;
    const int grp = lane >> 2, tig = lane & 3;
    const int wm = wid & 3, wn = wid >> 2;
    const int m0 = blockIdx.y * 128;
    const int n0 = blockIdx.x * 64;

    // ---- derive this cell's operands from (kdiag, z) ----
    const int l = lmin + blockIdx.z;
    const int t = kdiag - l;
    const size_t lsz = (size_t)BB * HH;
    const __nv_bfloat16* hb = reinterpret_cast<const __nv_bfloat16*>(g_hb32);
    __nv_bfloat16* hbw = reinterpret_cast<__nv_bfloat16*>(g_hb32);
    const __nv_bfloat16* wib = reinterpret_cast<const __nv_bfloat16*>(g_wib32);
    const __nv_bfloat16* whb = reinterpret_cast<const __nv_bfloat16*>(g_whb32);

    const __nv_bfloat16* h_prev = hb + (size_t)(l * 2 + ((t + 1) & 1)) * lsz;
    __nv_bfloat16*       h_o    = hbw + (size_t)(l * 2 + (t & 1)) * lsz;
    float*               cst    = g_c + (size_t)l * lsz;
    float*               ys     = (l == LL - 1) ? (g_ys + (size_t)t * HH) : nullptr;

    const __nv_bfloat16 *A0, *W0, *A1, *W1;
    const float *bih, *gx0;
    int nst;
    const float* bhh = bhh_g + l * G4;
    if (l == 0) {
        A0 = h_prev; W0 = whb; A1 = nullptr; W1 = nullptr;
        nst = 8; bih = nullptr; gx0 = g_gx0;
    } else {
        A0 = hb + (size_t)((l - 1) * 2 + (t & 1)) * lsz;
        W0 = wib + (size_t)l * G4 * HH;
        A1 = h_prev;
        W1 = whb + (size_t)l * G4 * HH;
        nst = 16; bih = bih_g + l * G4; gx0 = nullptr;
    }
    const int half = 8;

    float acc[2][8][4] = {};

    auto load_stage = [&](int s, int buf) {
        const __nv_bfloat16* A = A0; const __nv_bfloat16* W = W0; int kt = s * KT;
        if (s >= half) { A = A1; W = W1; kt = (s - half) * KT; }
        const uint32_t base = sbase + (uint32_t)buf * (STAGE_WORDS * 4);
        // A: 128 rows x 32 bf16 = 512 16B-chunks, one per thread
        {
            int r = tid >> 2, sub = tid & 3;
            cpasync16(base + (AOFFW + r * RSW + sub * 4) * 4,
                      A + (size_t)(m0 + r) * HH + kt + sub * 8);
        }
        // B: 256 rows x 32 bf16 = 1024 chunks, two per thread
#pragma unroll
        for (int i = 0; i < 2; i++) {
            int c = i * 512 + tid;
            int r = c >> 2, sub = c & 3;
            int wrow = (r >> 6) * HH + n0 + (r & 63);
            cpasync16(base + (BOFFW + r * RSW + sub * 4) * 4,
                      W + (size_t)wrow * HH + kt + sub * 8);
        }
    };

    auto compute = [&](int buf) {
        const uint32_t* sa = sm + buf * STAGE_WORDS + AOFFW;
        const uint32_t* sb = sm + buf * STAGE_WORDS + BOFFW;
#pragma unroll
        for (int kk = 0; kk < 2; kk++) {           // two k16 halves of the 32-k stage
            const int k0 = kk * 8;                  // word offset
            uint32_t af[2][4];
#pragma unroll
            for (int mt = 0; mt < 2; mt++) {
                int ra = wm * 32 + mt * 16 + grp;
                af[mt][0] = sa[ra * RSW + k0 + tig];
                af[mt][1] = sa[(ra + 8) * RSW + k0 + tig];
                af[mt][2] = sa[ra * RSW + k0 + tig + 4];
                af[mt][3] = sa[(ra + 8) * RSW + k0 + tig + 4];
            }
#pragma unroll
            for (int nt = 0; nt < 8; nt++) {
                int rb = wn * 64 + nt * 8 + grp;
                uint32_t b0 = sb[rb * RSW + k0 + tig];
                uint32_t b1 = sb[rb * RSW + k0 + tig + 4];
#pragma unroll
                for (int mt = 0; mt < 2; mt++)
                    mma16(acc[mt][nt], af[mt], b0, b1);
            }
        }
    };

    // ---- prologue: fill the 4-deep pipe (nst >= 8 always) ----
#pragma unroll
    for (int p = 0; p < NSTAGE; p++) {
        load_stage(p, p);
        CP_COMMIT();
    }

    for (int s = 0; s < nst; s++) {
        CP_WAIT3();
        __syncthreads();
        int buf = s & (NSTAGE - 1);
        compute(buf);
        __syncthreads();
        if (s + NSTAGE < nst) load_stage(s + NSTAGE, buf);
        CP_COMMIT();                 // empty tail groups keep accounting uniform
    }

    // ---- write gate pre-activations to smem (staging bufs dead now) ----
    float* smf = reinterpret_cast<float*>(sm);
#pragma unroll
    for (int mt = 0; mt < 2; mt++) {
#pragma unroll
        for (int nt = 0; nt < 8; nt++) {
            int row = wm * 32 + mt * 16 + grp;
            int col = wn * 64 + nt * 8 + 2 * tig;
            *reinterpret_cast<float2*>(&smf[row * GSTRIDE + col]) =
                make_float2(acc[mt][nt][0], acc[mt][nt][1]);
            *reinterpret_cast<float2*>(&smf[(row + 8) * GSTRIDE + col]) =
                make_float2(acc[mt][nt][2], acc[mt][nt][3]);
        }
    }
    __syncthreads();

    // ---------------- epilogue: LSTM cell, coalesced global I/O -------------
    const int u = tid & 63;
    const int n = n0 + u;
    const int bloc0 = (tid >> 6) * 16;   // 8 groups x 16 rows = 128

    float bsum[4];
#pragma unroll
    for (int gg = 0; gg < 4; gg++) {
        float v = bhh[gg * HH + n];
        if (bih) v += bih[gg * HH + n];
        bsum[gg] = v;
    }

    uint16_t* h_o16 = reinterpret_cast<uint16_t*>(h_o);
    for (int i = 0; i < 16; i++) {
        const int bl = bloc0 + i;
        const int gb = m0 + bl;
        float pre[4];
#pragma unroll
        for (int gg = 0; gg < 4; gg++)
            pre[gg] = smf[bl * GSTRIDE + gg * 64 + u] + bsum[gg];
        if (gx0) {
#pragma unroll
            for (int gg = 0; gg < 4; gg++)
                pre[gg] += gx0[(size_t)gb * G4 + gg * HH + n];
        }
        float co = cst[(size_t)gb * HH + n];
        float iv = sigf(pre[0]);
        float fv = sigf(pre[1]);
        float gv = tanh_fast(pre[2]);
        float ov = sigf(pre[3]);
        float cn = fv * co + iv * gv;
        float hn = ov * tanh_fast(cn);
        cst[(size_t)gb * HH + n] = cn;
        h_o16[(size_t)gb * HH + n] = __bfloat16_as_ushort(__float2bfloat16_rn(hn));
        if (ys) ys[(size_t)gb * (TT * HH) + n] = hn;
    }
}

// ---------------------------------------------------------------------------
// SIMT GEMM (small projections + output GEMM)
template <bool SIG>
__global__ __launch_bounds__(256) void gemm_bias_kernel(
    const float* __restrict__ A, const float* __restrict__ Wt,
    const float* __restrict__ bias, float* __restrict__ C,
    int M, int N, int K, int ldc)
{
    __shared__ float As[2][8][64];
    __shared__ float Bs[2][8][64];
    const int tid = threadIdx.x;
    const int tx = tid & 15, ty = tid >> 4;
    const int m0 = blockIdx.y * 64, n0 = blockIdx.x * 64;
    const int lr = tid >> 2, lc = (tid & 3) * 2;

    float acc[4][4] = {};

    auto load = [&](int tile, int buf) {
        int kt = tile * 8;
        float2 a2 = *reinterpret_cast<const float2*>(A + (size_t)(m0 + lr) * K + kt + lc);
        As[buf][lc][lr] = a2.x; As[buf][lc + 1][lr] = a2.y;
        float2 b2 = make_float2(0.0f, 0.0f);
        if (n0 + lr < N)
            b2 = *reinterpret_cast<const float2*>(Wt + (size_t)(n0 + lr) * K + kt + lc);
        Bs[buf][lc][lr] = b2.x; Bs[buf][lc + 1][lr] = b2.y;
    };

    const int ntiles = K >> 3;
    load(0, 0);
    __syncthreads();
    for (int tile = 0; tile < ntiles; ++tile) {
        int cur = tile & 1;
        if (tile + 1 < ntiles) load(tile + 1, cur ^ 1);
#pragma unroll
        for (int kk = 0; kk < 8; ++kk) {
            float4 av = *reinterpret_cast<const float4*>(&As[cur][kk][ty * 4]);
            float4 bv = *reinterpret_cast<const float4*>(&Bs[cur][kk][tx * 4]);
            float a[4] = {av.x, av.y, av.z, av.w};
            float bb[4] = {bv.x, bv.y, bv.z, bv.w};
#pragma unroll
            for (int mi = 0; mi < 4; ++mi)
#pragma unroll
                for (int ni = 0; ni < 4; ++ni)
                    acc[mi][ni] += a[mi] * bb[ni];
        }
        __syncthreads();
    }

#pragma unroll
    for (int mi = 0; mi < 4; ++mi) {
        int row = m0 + ty * 4 + mi;
#pragma unroll
        for (int ni = 0; ni < 4; ++ni) {
            int nn = n0 + tx * 4 + ni;
            if (nn < N) {
                float v = acc[mi][ni] + bias[nn];
                if (SIG) v = 1.0f / (1.0f + __expf(-v));
                C[(size_t)row * ldc + nn] = v;
            }
        }
    }
}

// ---------------------------------------------------------------------------
extern "C" void kernel_launch(void* const* d_in, const int* in_sizes, int n_in,
                              void* d_out, int out_size)
{
    const float* x   = (const float*)d_in[0];
    const float* lw  = (const float*)d_in[1];
    const float* lb  = (const float*)d_in[2];
    const float* wih = (const float*)d_in[3];
    const float* whh = (const float*)d_in[4];
    const float* bih = (const float*)d_in[5];
    const float* bhh = (const float*)d_in[6];
    const float* ow  = (const float*)d_in[7];
    const float* ob  = (const float*)d_in[8];
    float* out = (float*)d_out;

    float *cb, *xp, *gx0, *ys;
    uint32_t *hb32, *wib32, *whb32;
    cudaGetSymbolAddress((void**)&cb,    g_c);
    cudaGetSymbolAddress((void**)&xp,    g_xp);
    cudaGetSymbolAddress((void**)&gx0,   g_gx0);
    cudaGetSymbolAddress((void**)&ys,    g_ys);
    cudaGetSymbolAddress((void**)&hb32,  g_hb32);
    cudaGetSymbolAddress((void**)&wib32, g_wib32);
    cudaGetSymbolAddress((void**)&whb32, g_whb32);

    cudaFuncSetAttribute(cell_diag_kernel, cudaFuncAttributeMaxDynamicSharedMemorySize, SM_BYTES);

    // ---- state init + weight conversion (graph nodes, deterministic) ----
    zero_kernel<<<2048, 256>>>((float*)hb32, LL * BB * HH);   // bf16 zeros (whole parity-buffered state)
    zero_kernel<<<2048, 256>>>(cb, LL * BB * HH);
    f2bf_kernel<<<1024, 256>>>(wih, wib32, LL * G4 * HH / 2);
    f2bf_kernel<<<1024, 256>>>(whh, whb32, LL * G4 * HH / 2);

    // xp = x @ lw.T + lb
    gemm_bias_kernel<false><<<dim3(HH / 64, BB / 64), 256>>>(x, lw, lb, xp, BB, HH, LATENT, HH);
    // gx0 = xp @ wih[0].T + bih[0]  (constant over time, fp32)
    gemm_bias_kernel<false><<<dim3(G4 / 64, BB / 64), 256>>>(xp, wih, bih, gx0, BB, G4, HH, G4);

    // ---- wavefront over diagonals k = l + t ----
    for (int k = 0; k < TT + LL - 1; ++k) {
        int lmin = k - (TT - 1); if (lmin < 0) lmin = 0;
        int lmax = k;            if (lmax > LL - 1) lmax = LL - 1;
        dim3 grid(4, 32, (unsigned)(lmax - lmin + 1));
        cell_diag_kernel<<<grid, 512, SM_BYTES>>>(k, lmin, bih, bhh);
    }

    // out = sigmoid(ys @ ow.T + ob)
    gemm_bias_kernel<true><<<dim3((OUTN + 63) / 64, (BB * TT) / 64), 256>>>(
        ys, ow, ob, out, BB * TT, OUTN, HH, OUTN);
}

// round 11
// speedup vs baseline: 4.7099x; 1.0636x over previous
#include <cuda_runtime.h>
#include <cuda_bf16.h>
#include <math.h>
#include <stdint.h>

#define BB     4096
#define LATENT 128
#define HH     256
#define G4     1024   // 4*HH
#define OUTN   88
#define TT     64
#define LL     5

// ---------------- static device scratch (no allocations allowed) -------------
__device__ float    g_c[LL * BB * HH];
__device__ float    g_xp[BB * HH];
__device__ float    g_gx0[BB * G4];              // layer-0 input gates (const over t)
__device__ float    g_ys[BB * TT * HH];          // [B][T][H] fp32
__device__ uint32_t g_hb32[LL * 2 * BB * HH / 2];   // h state, bf16 pairs, parity buffered
__device__ uint32_t g_wib32[LL * G4 * HH / 2];      // wih in bf16 pairs
__device__ uint32_t g_whb32[LL * G4 * HH / 2];      // whh in bf16 pairs

// ---------------------------------------------------------------------------
__global__ void zero_kernel(float* __restrict__ p, int n) {
    int i = blockIdx.x * blockDim.x + threadIdx.x;
    int stride = gridDim.x * blockDim.x;
    for (; i < n; i += stride) p[i] = 0.0f;
}

// fp32 -> packed bf16x2 conversion (n2 = number of OUTPUT words)
__global__ void f2bf_kernel(const float* __restrict__ in, uint32_t* __restrict__ out, int n2) {
    int i = blockIdx.x * blockDim.x + threadIdx.x;
    int stride = gridDim.x * blockDim.x;
    for (; i < n2; i += stride) {
        uint32_t lo = (uint32_t)__bfloat16_as_ushort(__float2bfloat16_rn(in[2 * i]));
        uint32_t hi = (uint32_t)__bfloat16_as_ushort(__float2bfloat16_rn(in[2 * i + 1]));
        out[i] = lo | (hi << 16);
    }
}

__device__ __forceinline__ float sigf(float x) { return 1.0f / (1.0f + __expf(-x)); }
__device__ __forceinline__ float tanh_fast(float x) {
    float t = __expf(-2.0f * fabsf(x));
    float r = (1.0f - t) / (1.0f + t);
    return copysignf(r, x);
}
__device__ __forceinline__ void mma16(float* d, const uint32_t* a, uint32_t b0, uint32_t b1) {
    asm volatile(
        "mma.sync.aligned.m16n8k16.row.col.f32.bf16.bf16.f32 "
        "{%0,%1,%2,%3},{%4,%5,%6,%7},{%8,%9},{%0,%1,%2,%3};"
        : "+f"(d[0]), "+f"(d[1]), "+f"(d[2]), "+f"(d[3])
        : "r"(a[0]), "r"(a[1]), "r"(a[2]), "r"(a[3]), "r"(b0), "r"(b1));
}
__device__ __forceinline__ void ldm4(uint32_t* r, uint32_t addr) {
    asm volatile("ldmatrix.sync.aligned.m8n8.x4.shared.b16 {%0,%1,%2,%3}, [%4];"
                 : "=r"(r[0]), "=r"(r[1]), "=r"(r[2]), "=r"(r[3]) : "r"(addr));
}
__device__ __forceinline__ uint32_t smem_u32(const void* p) {
    uint32_t a;
    asm("{ .reg .u64 t; cvta.to.shared.u64 t, %1; cvt.u32.u64 %0, t; }" : "=r"(a) : "l"(p));
    return a;
}
__device__ __forceinline__ void cpasync16(uint32_t dst, const void* src) {
    asm volatile("cp.async.cg.shared.global [%0], [%1], 16;" :: "r"(dst), "l"(src) : "memory");
}
#define CP_COMMIT() asm volatile("cp.async.commit_group;" ::: "memory")
#define CP_WAIT2()  asm volatile("cp.async.wait_group 2;" ::: "memory")

// ---------------------------------------------------------------------------
// Wavefront-fused bf16 mma.sync LSTM cell.
// One launch per diagonal k = l + t; blockIdx.z enumerates the independent
// cells. CTA tile: 128 batch x 256 gate-cols (4 gates x 64 units); 512 threads,
// 16 warps (4m x 4n), warp tile 32x64 via m16n8k16. Fragments fed by
// ldmatrix.x4; cp.async 4-buffer/3-in-flight pipeline, ONE barrier per stage.
// Accumulation + nonlinearity in fp32.
// ---------------------------------------------------------------------------
#define KT          32                 // bf16 k-elems per stage
#define RSW         20                 // row stride in 32-bit words (32 bf16 + 8 pad)
#define AROWS       128
#define BROWS       256
#define STAGE_WORDS ((AROWS + BROWS) * RSW)   // 7680 words = 30720 B
#define AOFFW       0
#define BOFFW       (AROWS * RSW)      // 2560
#define NSTAGE      4
#define GSTRIDE     258                // epilogue gate buffer row stride (floats)
#define SM_WORDS    (AROWS * GSTRIDE)  // 33024 words = 132096 B (> 4*7680=30720)
#define SM_BYTES    (SM_WORDS * 4)

__global__ __launch_bounds__(512, 1) void cell_diag_kernel(
    int kdiag, int lmin,
    const float* __restrict__ bih_g, const float* __restrict__ bhh_g)
{
    extern __shared__ uint32_t sm[];
    const uint32_t sbase = smem_u32(sm);
    const int tid = threadIdx.x;
    const int wid = tid >> 5, lane = tid & 31;
    const int grp = lane >> 2, tig = lane & 3;
    const int wm = wid & 3, wn = wid >> 2;
    const int m0 = blockIdx.y * 128;
    const int n0 = blockIdx.x * 64;

    // ldmatrix lane decomposition: q = lane>>3 selects the 8x8 sub-matrix,
    // rlane = lane&7 the row within it.
    const int q = lane >> 3, rlane = lane & 7;
    const int ldm_row = rlane + (q & 1) * 8;     // row offset within 16-row tile
    const int ldm_colw = (q >> 1) * 4;           // word offset: 0 or 4 (16B halves)

    // ---- derive this cell's operands from (kdiag, z) ----
    const int l = lmin + blockIdx.z;
    const int t = kdiag - l;
    const size_t lsz = (size_t)BB * HH;
    const __nv_bfloat16* hb = reinterpret_cast<const __nv_bfloat16*>(g_hb32);
    __nv_bfloat16* hbw = reinterpret_cast<__nv_bfloat16*>(g_hb32);
    const __nv_bfloat16* wib = reinterpret_cast<const __nv_bfloat16*>(g_wib32);
    const __nv_bfloat16* whb = reinterpret_cast<const __nv_bfloat16*>(g_whb32);

    const __nv_bfloat16* h_prev = hb + (size_t)(l * 2 + ((t + 1) & 1)) * lsz;
    __nv_bfloat16*       h_o    = hbw + (size_t)(l * 2 + (t & 1)) * lsz;
    float*               cst    = g_c + (size_t)l * lsz;
    float*               ys     = (l == LL - 1) ? (g_ys + (size_t)t * HH) : nullptr;

    const __nv_bfloat16 *A0, *W0, *A1, *W1;
    const float *bih, *gx0;
    int nst;
    const float* bhh = bhh_g + l * G4;
    if (l == 0) {
        A0 = h_prev; W0 = whb; A1 = nullptr; W1 = nullptr;
        nst = 8; bih = nullptr; gx0 = g_gx0;
    } else {
        A0 = hb + (size_t)((l - 1) * 2 + (t & 1)) * lsz;
        W0 = wib + (size_t)l * G4 * HH;
        A1 = h_prev;
        W1 = whb + (size_t)l * G4 * HH;
        nst = 16; bih = bih_g + l * G4; gx0 = nullptr;
    }
    const int half = 8;

    float acc[2][8][4] = {};

    auto load_stage = [&](int s, int buf) {
        const __nv_bfloat16* A = A0; const __nv_bfloat16* W = W0; int kt = s * KT;
        if (s >= half) { A = A1; W = W1; kt = (s - half) * KT; }
        const uint32_t base = sbase + (uint32_t)buf * (STAGE_WORDS * 4);
        // A: 128 rows x 32 bf16 = 512 16B-chunks, one per thread
        {
            int r = tid >> 2, sub = tid & 3;
            cpasync16(base + (AOFFW + r * RSW + sub * 4) * 4,
                      A + (size_t)(m0 + r) * HH + kt + sub * 8);
        }
        // B: 256 rows x 32 bf16 = 1024 chunks, two per thread
#pragma unroll
        for (int i = 0; i < 2; i++) {
            int c = i * 512 + tid;
            int r = c >> 2, sub = c & 3;
            int wrow = (r >> 6) * HH + n0 + (r & 63);
            cpasync16(base + (BOFFW + r * RSW + sub * 4) * 4,
                      W + (size_t)wrow * HH + kt + sub * 8);
        }
    };

    auto compute = [&](int buf) {
        const uint32_t sa = sbase + (uint32_t)buf * (STAGE_WORDS * 4) + AOFFW * 4;
        const uint32_t sb = sbase + (uint32_t)buf * (STAGE_WORDS * 4) + BOFFW * 4;
#pragma unroll
        for (int kk = 0; kk < 2; kk++) {           // two k16 halves of the 32-k stage
            const int k0 = kk * 8;                  // word offset
            uint32_t af[2][4];
#pragma unroll
            for (int mt = 0; mt < 2; mt++) {
                int ra = wm * 32 + mt * 16;
                ldm4(af[mt], sa + ((ra + ldm_row) * RSW + k0 + ldm_colw) * 4);
            }
            uint32_t bf[8][2];
#pragma unroll
            for (int ntp = 0; ntp < 4; ntp++) {
                int rb = wn * 64 + ntp * 16;
                uint32_t r4[4];
                ldm4(r4, sb + ((rb + ldm_row) * RSW + k0 + ldm_colw) * 4);
                bf[2 * ntp][0] = r4[0]; bf[2 * ntp + 1][0] = r4[1];
                bf[2 * ntp][1] = r4[2]; bf[2 * ntp + 1][1] = r4[3];
            }
#pragma unroll
            for (int nt = 0; nt < 8; nt++)
#pragma unroll
                for (int mt = 0; mt < 2; mt++)
                    mma16(acc[mt][nt], af[mt], bf[nt][0], bf[nt][1]);
        }
    };

    // ---- prologue: 3 stages in flight (nst >= 8 always) ----
#pragma unroll
    for (int p = 0; p < 3; p++) {
        load_stage(p, p);
        CP_COMMIT();
    }

    // ---- mainloop: ONE barrier per stage ----
    for (int s = 0; s < nst; s++) {
        CP_WAIT2();
        __syncthreads();
        // issue stage s+3 into buf (s+3)%4 == (s-1)%4; every warp passed the
        // sync above only after finishing compute(s-1), the last reader.
        if (s + 3 < nst) load_stage(s + 3, (s + 3) & (NSTAGE - 1));
        CP_COMMIT();                 // empty tail groups keep accounting uniform
        compute(s & (NSTAGE - 1));
    }
    __syncthreads();                 // protect gate-buffer overwrite of staging

    // ---- write gate pre-activations to smem (staging bufs dead now) ----
    float* smf = reinterpret_cast<float*>(sm);
#pragma unroll
    for (int mt = 0; mt < 2; mt++) {
#pragma unroll
        for (int nt = 0; nt < 8; nt++) {
            int row = wm * 32 + mt * 16 + grp;
            int col = wn * 64 + nt * 8 + 2 * tig;
            *reinterpret_cast<float2*>(&smf[row * GSTRIDE + col]) =
                make_float2(acc[mt][nt][0], acc[mt][nt][1]);
            *reinterpret_cast<float2*>(&smf[(row + 8) * GSTRIDE + col]) =
                make_float2(acc[mt][nt][2], acc[mt][nt][3]);
        }
    }
    __syncthreads();

    // ---------------- epilogue: LSTM cell, coalesced global I/O -------------
    const int u = tid & 63;
    const int n = n0 + u;
    const int bloc0 = (tid >> 6) * 16;   // 8 groups x 16 rows = 128

    float bsum[4];
#pragma unroll
    for (int gg = 0; gg < 4; gg++) {
        float v = bhh[gg * HH + n];
        if (bih) v += bih[gg * HH + n];
        bsum[gg] = v;
    }

    uint16_t* h_o16 = reinterpret_cast<uint16_t*>(h_o);
    for (int i = 0; i < 16; i++) {
        const int bl = bloc0 + i;
        const int gb = m0 + bl;
        float pre[4];
#pragma unroll
        for (int gg = 0; gg < 4; gg++)
            pre[gg] = smf[bl * GSTRIDE + gg * 64 + u] + bsum[gg];
        if (gx0) {
#pragma unroll
            for (int gg = 0; gg < 4; gg++)
                pre[gg] += gx0[(size_t)gb * G4 + gg * HH + n];
        }
        float co = cst[(size_t)gb * HH + n];
        float iv = sigf(pre[0]);
        float fv = sigf(pre[1]);
        float gv = tanh_fast(pre[2]);
        float ov = sigf(pre[3]);
        float cn = fv * co + iv * gv;
        float hn = ov * tanh_fast(cn);
        cst[(size_t)gb * HH + n] = cn;
        h_o16[(size_t)gb * HH + n] = __bfloat16_as_ushort(__float2bfloat16_rn(hn));
        if (ys) ys[(size_t)gb * (TT * HH) + n] = hn;
    }
}

// ---------------------------------------------------------------------------
// SIMT GEMM (small projections + output GEMM)
template <bool SIG>
__global__ __launch_bounds__(256) void gemm_bias_kernel(
    const float* __restrict__ A, const float* __restrict__ Wt,
    const float* __restrict__ bias, float* __restrict__ C,
    int M, int N, int K, int ldc)
{
    __shared__ float As[2][8][64];
    __shared__ float Bs[2][8][64];
    const int tid = threadIdx.x;
    const int tx = tid & 15, ty = tid >> 4;
    const int m0 = blockIdx.y * 64, n0 = blockIdx.x * 64;
    const int lr = tid >> 2, lc = (tid & 3) * 2;

    float acc[4][4] = {};

    auto load = [&](int tile, int buf) {
        int kt = tile * 8;
        float2 a2 = *reinterpret_cast<const float2*>(A + (size_t)(m0 + lr) * K + kt + lc);
        As[buf][lc][lr] = a2.x; As[buf][lc + 1][lr] = a2.y;
        float2 b2 = make_float2(0.0f, 0.0f);
        if (n0 + lr < N)
            b2 = *reinterpret_cast<const float2*>(Wt + (size_t)(n0 + lr) * K + kt + lc);
        Bs[buf][lc][lr] = b2.x; Bs[buf][lc + 1][lr] = b2.y;
    };

    const int ntiles = K >> 3;
    load(0, 0);
    __syncthreads();
    for (int tile = 0; tile < ntiles; ++tile) {
        int cur = tile & 1;
        if (tile + 1 < ntiles) load(tile + 1, cur ^ 1);
#pragma unroll
        for (int kk = 0; kk < 8; ++kk) {
            float4 av = *reinterpret_cast<const float4*>(&As[cur][kk][ty * 4]);
            float4 bv = *reinterpret_cast<const float4*>(&Bs[cur][kk][tx * 4]);
            float a[4] = {av.x, av.y, av.z, av.w};
            float bb[4] = {bv.x, bv.y, bv.z, bv.w};
#pragma unroll
            for (int mi = 0; mi < 4; ++mi)
#pragma unroll
                for (int ni = 0; ni < 4; ++ni)
                    acc[mi][ni] += a[mi] * bb[ni];
        }
        __syncthreads();
    }

#pragma unroll
    for (int mi = 0; mi < 4; ++mi) {
        int row = m0 + ty * 4 + mi;
#pragma unroll
        for (int ni = 0; ni < 4; ++ni) {
            int nn = n0 + tx * 4 + ni;
            if (nn < N) {
                float v = acc[mi][ni] + bias[nn];
                if (SIG) v = 1.0f / (1.0f + __expf(-v));
                C[(size_t)row * ldc + nn] = v;
            }
        }
    }
}

// ---------------------------------------------------------------------------
extern "C" void kernel_launch(void* const* d_in, const int* in_sizes, int n_in,
                              void* d_out, int out_size)
{
    const float* x   = (const float*)d_in[0];
    const float* lw  = (const float*)d_in[1];
    const float* lb  = (const float*)d_in[2];
    const float* wih = (const float*)d_in[3];
    const float* whh = (const float*)d_in[4];
    const float* bih = (const float*)d_in[5];
    const float* bhh = (const float*)d_in[6];
    const float* ow  = (const float*)d_in[7];
    const float* ob  = (const float*)d_in[8];
    float* out = (float*)d_out;

    float *cb, *xp, *gx0, *ys;
    uint32_t *hb32, *wib32, *whb32;
    cudaGetSymbolAddress((void**)&cb,    g_c);
    cudaGetSymbolAddress((void**)&xp,    g_xp);
    cudaGetSymbolAddress((void**)&gx0,   g_gx0);
    cudaGetSymbolAddress((void**)&ys,    g_ys);
    cudaGetSymbolAddress((void**)&hb32,  g_hb32);
    cudaGetSymbolAddress((void**)&wib32, g_wib32);
    cudaGetSymbolAddress((void**)&whb32, g_whb32);

    cudaFuncSetAttribute(cell_diag_kernel, cudaFuncAttributeMaxDynamicSharedMemorySize, SM_BYTES);

    // ---- state init + weight conversion (graph nodes, deterministic) ----
    zero_kernel<<<2048, 256>>>((float*)hb32, LL * BB * HH);   // bf16 zeros (whole parity-buffered state)
    zero_kernel<<<2048, 256>>>(cb, LL * BB * HH);
    f2bf_kernel<<<1024, 256>>>(wih, wib32, LL * G4 * HH / 2);
    f2bf_kernel<<<1024, 256>>>(whh, whb32, LL * G4 * HH / 2);

    // xp = x @ lw.T + lb
    gemm_bias_kernel<false><<<dim3(HH / 64, BB / 64), 256>>>(x, lw, lb, xp, BB, HH, LATENT, HH);
    // gx0 = xp @ wih[0].T + bih[0]  (constant over time, fp32)
    gemm_bias_kernel<false><<<dim3(G4 / 64, BB / 64), 256>>>(xp, wih, bih, gx0, BB, G4, HH, G4);

    // ---- wavefront over diagonals k = l + t ----
    for (int k = 0; k < TT + LL - 1; ++k) {
        int lmin = k - (TT - 1); if (lmin < 0) lmin = 0;
        int lmax = k;            if (lmax > LL - 1) lmax = LL - 1;
        dim3 grid(4, 32, (unsigned)(lmax - lmin + 1));
        cell_diag_kernel<<<grid, 512, SM_BYTES>>>(k, lmin, bih, bhh);
    }

    // out = sigmoid(ys @ ow.T + ob)
    gemm_bias_kernel<true><<<dim3((OUTN + 63) / 64, (BB * TT) / 64), 256>>>(
        ys, ow, ob, out, BB * TT, OUTN, HH, OUTN);
}

// round 12
// speedup vs baseline: 4.9310x; 1.0469x over previous
#include <cuda_runtime.h>
#include <cuda_bf16.h>
#include <math.h>
#include <stdint.h>

#define BB     4096
#define LATENT 128
#define HH     256
#define G4     1024   // 4*HH
#define OUTN   88
#define TT     64
#define LL     5

// ---------------- static device scratch (no allocations allowed) -------------
__device__ float    g_c[LL * BB * HH];
__device__ float    g_xp[BB * HH];
__device__ float    g_gx0[BB * G4];              // layer-0 input gates (const over t)
__device__ float    g_ys[BB * TT * HH];          // [B][T][H] fp32
__device__ uint32_t g_hb32[LL * 2 * BB * HH / 2];   // h state, bf16 pairs, parity buffered
__device__ uint32_t g_wib32[LL * G4 * HH / 2];      // wih in bf16 pairs
__device__ uint32_t g_whb32[LL * G4 * HH / 2];      // whh in bf16 pairs

// ---------------------------------------------------------------------------
__global__ void zero_kernel(float* __restrict__ p, int n) {
    int i = blockIdx.x * blockDim.x + threadIdx.x;
    int stride = gridDim.x * blockDim.x;
    for (; i < n; i += stride) p[i] = 0.0f;
}

// fp32 -> packed bf16x2 conversion (n2 = number of OUTPUT words)
__global__ void f2bf_kernel(const float* __restrict__ in, uint32_t* __restrict__ out, int n2) {
    int i = blockIdx.x * blockDim.x + threadIdx.x;
    int stride = gridDim.x * blockDim.x;
    for (; i < n2; i += stride) {
        uint32_t lo = (uint32_t)__bfloat16_as_ushort(__float2bfloat16_rn(in[2 * i]));
        uint32_t hi = (uint32_t)__bfloat16_as_ushort(__float2bfloat16_rn(in[2 * i + 1]));
        out[i] = lo | (hi << 16);
    }
}

__device__ __forceinline__ float sigf(float x) { return 1.0f / (1.0f + __expf(-x)); }
__device__ __forceinline__ float tanh_fast(float x) {
    float t = __expf(-2.0f * fabsf(x));
    float r = (1.0f - t) / (1.0f + t);
    return copysignf(r, x);
}
__device__ __forceinline__ void mma16(float* d, const uint32_t* a, uint32_t b0, uint32_t b1) {
    asm volatile(
        "mma.sync.aligned.m16n8k16.row.col.f32.bf16.bf16.f32 "
        "{%0,%1,%2,%3},{%4,%5,%6,%7},{%8,%9},{%0,%1,%2,%3};"
        : "+f"(d[0]), "+f"(d[1]), "+f"(d[2]), "+f"(d[3])
        : "r"(a[0]), "r"(a[1]), "r"(a[2]), "r"(a[3]), "r"(b0), "r"(b1));
}
__device__ __forceinline__ void ldm4(uint32_t* r, uint32_t addr) {
    asm volatile("ldmatrix.sync.aligned.m8n8.x4.shared.b16 {%0,%1,%2,%3}, [%4];"
                 : "=r"(r[0]), "=r"(r[1]), "=r"(r[2]), "=r"(r[3]) : "r"(addr));
}
__device__ __forceinline__ uint32_t smem_u32(const void* p) {
    uint32_t a;
    asm("{ .reg .u64 t; cvta.to.shared.u64 t, %1; cvt.u32.u64 %0, t; }" : "=r"(a) : "l"(p));
    return a;
}
__device__ __forceinline__ void cpasync16(uint32_t dst, const void* src) {
    asm volatile("cp.async.cg.shared.global [%0], [%1], 16;" :: "r"(dst), "l"(src) : "memory");
}
#define CP_COMMIT() asm volatile("cp.async.commit_group;" ::: "memory")
#define CP_WAIT1()  asm volatile("cp.async.wait_group 1;" ::: "memory")

// ---------------------------------------------------------------------------
// Wavefront-fused bf16 mma.sync LSTM cell.
// One launch per diagonal k = l + t; blockIdx.z enumerates the independent
// cells. CTA tile: 128 batch x 256 gate-cols (4 gates x 64 units); 512 threads,
// 16 warps (4m x 4n), warp tile 32x64 via m16n8k16. Fragments via ldmatrix.x4.
// K staged 64 bf16 per stage (halves stage-boundary overhead vs KT=32);
// 3 smem buffers, 2-stage-ahead cp.async prefetch, ONE barrier per stage.
// Accumulation + nonlinearity in fp32.
// ---------------------------------------------------------------------------
#define KT          64                 // bf16 k-elems per stage
#define RSW         36                 // row stride in words (32 data + 4 pad; 144B, 16B-aligned)
#define AROWS       128
#define BROWS       256
#define STAGE_WORDS ((AROWS + BROWS) * RSW)   // 13824 words = 55296 B
#define AOFFW       0
#define BOFFW       (AROWS * RSW)      // 4608
#define NSTAGE      3
#define GSTRIDE     258                // epilogue gate buffer row stride (floats)
#define SM_WORDS    (NSTAGE * STAGE_WORDS)    // 41472 words = 165888 B (> 128*258=33024)
#define SM_BYTES    (SM_WORDS * 4)

__global__ __launch_bounds__(512, 1) void cell_diag_kernel(
    int kdiag, int lmin,
    const float* __restrict__ bih_g, const float* __restrict__ bhh_g)
{
    extern __shared__ uint32_t sm[];
    const uint32_t sbase = smem_u32(sm);
    const int tid = threadIdx.x;
    const int wid = tid >> 5, lane = tid & 31;
    const int grp = lane >> 2, tig = lane & 3;
    const int wm = wid & 3, wn = wid >> 2;
    const int m0 = blockIdx.y * 128;
    const int n0 = blockIdx.x * 64;

    // ldmatrix lane decomposition
    const int q = lane >> 3, rlane = lane & 7;
    const int ldm_row = rlane + (q & 1) * 8;     // row offset within 16-row tile
    const int ldm_colw = (q >> 1) * 4;           // word offset: 0 or 4 (16B halves)

    // ---- derive this cell's operands from (kdiag, z) ----
    const int l = lmin + blockIdx.z;
    const int t = kdiag - l;
    const size_t lsz = (size_t)BB * HH;
    const __nv_bfloat16* hb = reinterpret_cast<const __nv_bfloat16*>(g_hb32);
    __nv_bfloat16* hbw = reinterpret_cast<__nv_bfloat16*>(g_hb32);
    const __nv_bfloat16* wib = reinterpret_cast<const __nv_bfloat16*>(g_wib32);
    const __nv_bfloat16* whb = reinterpret_cast<const __nv_bfloat16*>(g_whb32);

    const __nv_bfloat16* h_prev = hb + (size_t)(l * 2 + ((t + 1) & 1)) * lsz;
    __nv_bfloat16*       h_o    = hbw + (size_t)(l * 2 + (t & 1)) * lsz;
    float*               cst    = g_c + (size_t)l * lsz;
    float*               ys     = (l == LL - 1) ? (g_ys + (size_t)t * HH) : nullptr;

    const __nv_bfloat16 *A0, *W0, *A1, *W1;
    const float *bih, *gx0;
    int nst;
    const float* bhh = bhh_g + l * G4;
    if (l == 0) {
        A0 = h_prev; W0 = whb; A1 = nullptr; W1 = nullptr;
        nst = 4; bih = nullptr; gx0 = g_gx0;
    } else {
        A0 = hb + (size_t)((l - 1) * 2 + (t & 1)) * lsz;
        W0 = wib + (size_t)l * G4 * HH;
        A1 = h_prev;
        W1 = whb + (size_t)l * G4 * HH;
        nst = 8; bih = bih_g + l * G4; gx0 = nullptr;
    }
    const int half = 4;

    float acc[2][8][4] = {};

    auto load_stage = [&](int s, int buf) {
        const __nv_bfloat16* A = A0; const __nv_bfloat16* W = W0; int kt = s * KT;
        if (s >= half) { A = A1; W = W1; kt = (s - half) * KT; }
        const uint32_t base = sbase + (uint32_t)buf * (STAGE_WORDS * 4);
        // A: 128 rows x 64 bf16 = 1024 16B-chunks, two per thread
#pragma unroll
        for (int i = 0; i < 2; i++) {
            int c = i * 512 + tid;
            int r = c >> 3, sub = c & 7;
            cpasync16(base + (AOFFW + r * RSW + sub * 4) * 4,
                      A + (size_t)(m0 + r) * HH + kt + sub * 8);
        }
        // B: 256 rows x 64 bf16 = 2048 chunks, four per thread
#pragma unroll
        for (int i = 0; i < 4; i++) {
            int c = i * 512 + tid;
            int r = c >> 3, sub = c & 7;
            int wrow = (r >> 6) * HH + n0 + (r & 63);
            cpasync16(base + (BOFFW + r * RSW + sub * 4) * 4,
                      W + (size_t)wrow * HH + kt + sub * 8);
        }
    };

    auto compute = [&](int buf) {
        const uint32_t sa = sbase + (uint32_t)buf * (STAGE_WORDS * 4) + AOFFW * 4;
        const uint32_t sb = sbase + (uint32_t)buf * (STAGE_WORDS * 4) + BOFFW * 4;
#pragma unroll
        for (int kk = 0; kk < 4; kk++) {           // four k16 halves of the 64-k stage
            const int k0 = kk * 8;                  // word offset
            uint32_t af[2][4];
#pragma unroll
            for (int mt = 0; mt < 2; mt++) {
                int ra = wm * 32 + mt * 16;
                ldm4(af[mt], sa + ((ra + ldm_row) * RSW + k0 + ldm_colw) * 4);
            }
            uint32_t bf[8][2];
#pragma unroll
            for (int ntp = 0; ntp < 4; ntp++) {
                int rb = wn * 64 + ntp * 16;
                uint32_t r4[4];
                ldm4(r4, sb + ((rb + ldm_row) * RSW + k0 + ldm_colw) * 4);
                bf[2 * ntp][0] = r4[0]; bf[2 * ntp + 1][0] = r4[1];
                bf[2 * ntp][1] = r4[2]; bf[2 * ntp + 1][1] = r4[3];
            }
#pragma unroll
            for (int nt = 0; nt < 8; nt++)
#pragma unroll
                for (int mt = 0; mt < 2; mt++)
                    mma16(acc[mt][nt], af[mt], bf[nt][0], bf[nt][1]);
        }
    };

    // ---- prologue: 2 stages in flight (nst >= 4 always) ----
#pragma unroll
    for (int p = 0; p < 2; p++) {
        load_stage(p, p);
        CP_COMMIT();
    }

    // ---- mainloop: ONE barrier per stage, 3 buffers, 2-ahead prefetch ----
    for (int s = 0; s < nst; s++) {
        CP_WAIT1();                 // stage s complete (newest group may be in flight)
        __syncthreads();
        // load stage s+2 into buf (s+2)%3 == (s-1)%3; every warp passed the
        // barrier only after finishing compute(s-1), the last reader.
        if (s + 2 < nst) load_stage(s + 2, (s + 2) % NSTAGE);
        CP_COMMIT();                // empty tail groups keep accounting uniform
        compute(s % NSTAGE);
    }
    __syncthreads();                // protect gate-buffer overwrite of staging

    // ---- write gate pre-activations to smem (staging bufs dead now) ----
    float* smf = reinterpret_cast<float*>(sm);
#pragma unroll
    for (int mt = 0; mt < 2; mt++) {
#pragma unroll
        for (int nt = 0; nt < 8; nt++) {
            int row = wm * 32 + mt * 16 + grp;
            int col = wn * 64 + nt * 8 + 2 * tig;
            *reinterpret_cast<float2*>(&smf[row * GSTRIDE + col]) =
                make_float2(acc[mt][nt][0], acc[mt][nt][1]);
            *reinterpret_cast<float2*>(&smf[(row + 8) * GSTRIDE + col]) =
                make_float2(acc[mt][nt][2], acc[mt][nt][3]);
        }
    }
    __syncthreads();

    // ---------------- epilogue: LSTM cell, coalesced global I/O -------------
    const int u = tid & 63;
    const int n = n0 + u;
    const int bloc0 = (tid >> 6) * 16;   // 8 groups x 16 rows = 128

    float bsum[4];
#pragma unroll
    for (int gg = 0; gg < 4; gg++) {
        float v = bhh[gg * HH + n];
        if (bih) v += bih[gg * HH + n];
        bsum[gg] = v;
    }

    uint16_t* h_o16 = reinterpret_cast<uint16_t*>(h_o);
    for (int i = 0; i < 16; i++) {
        const int bl = bloc0 + i;
        const int gb = m0 + bl;
        float pre[4];
#pragma unroll
        for (int gg = 0; gg < 4; gg++)
            pre[gg] = smf[bl * GSTRIDE + gg * 64 + u] + bsum[gg];
        if (gx0) {
#pragma unroll
            for (int gg = 0; gg < 4; gg++)
                pre[gg] += gx0[(size_t)gb * G4 + gg * HH + n];
        }
        float co = cst[(size_t)gb * HH + n];
        float iv = sigf(pre[0]);
        float fv = sigf(pre[1]);
        float gv = tanh_fast(pre[2]);
        float ov = sigf(pre[3]);
        float cn = fv * co + iv * gv;
        float hn = ov * tanh_fast(cn);
        cst[(size_t)gb * HH + n] = cn;
        h_o16[(size_t)gb * HH + n] = __bfloat16_as_ushort(__float2bfloat16_rn(hn));
        if (ys) ys[(size_t)gb * (TT * HH) + n] = hn;
    }
}

// ---------------------------------------------------------------------------
// SIMT GEMM (small projections + output GEMM)
template <bool SIG>
__global__ __launch_bounds__(256) void gemm_bias_kernel(
    const float* __restrict__ A, const float* __restrict__ Wt,
    const float* __restrict__ bias, float* __restrict__ C,
    int M, int N, int K, int ldc)
{
    __shared__ float As[2][8][64];
    __shared__ float Bs[2][8][64];
    const int tid = threadIdx.x;
    const int tx = tid & 15, ty = tid >> 4;
    const int m0 = blockIdx.y * 64, n0 = blockIdx.x * 64;
    const int lr = tid >> 2, lc = (tid & 3) * 2;

    float acc[4][4] = {};

    auto load = [&](int tile, int buf) {
        int kt = tile * 8;
        float2 a2 = *reinterpret_cast<const float2*>(A + (size_t)(m0 + lr) * K + kt + lc);
        As[buf][lc][lr] = a2.x; As[buf][lc + 1][lr] = a2.y;
        float2 b2 = make_float2(0.0f, 0.0f);
        if (n0 + lr < N)
            b2 = *reinterpret_cast<const float2*>(Wt + (size_t)(n0 + lr) * K + kt + lc);
        Bs[buf][lc][lr] = b2.x; Bs[buf][lc + 1][lr] = b2.y;
    };

    const int ntiles = K >> 3;
    load(0, 0);
    __syncthreads();
    for (int tile = 0; tile < ntiles; ++tile) {
        int cur = tile & 1;
        if (tile + 1 < ntiles) load(tile + 1, cur ^ 1);
#pragma unroll
        for (int kk = 0; kk < 8; ++kk) {
            float4 av = *reinterpret_cast<const float4*>(&As[cur][kk][ty * 4]);
            float4 bv = *reinterpret_cast<const float4*>(&Bs[cur][kk][tx * 4]);
            float a[4] = {av.x, av.y, av.z, av.w};
            float bb[4] = {bv.x, bv.y, bv.z, bv.w};
#pragma unroll
            for (int mi = 0; mi < 4; ++mi)
#pragma unroll
                for (int ni = 0; ni < 4; ++ni)
                    acc[mi][ni] += a[mi] * bb[ni];
        }
        __syncthreads();
    }

#pragma unroll
    for (int mi = 0; mi < 4; ++mi) {
        int row = m0 + ty * 4 + mi;
#pragma unroll
        for (int ni = 0; ni < 4; ++ni) {
            int nn = n0 + tx * 4 + ni;
            if (nn < N) {
                float v = acc[mi][ni] + bias[nn];
                if (SIG) v = 1.0f / (1.0f + __expf(-v));
                C[(size_t)row * ldc + nn] = v;
            }
        }
    }
}

// ---------------------------------------------------------------------------
extern "C" void kernel_launch(void* const* d_in, const int* in_sizes, int n_in,
                              void* d_out, int out_size)
{
    const float* x   = (const float*)d_in[0];
    const float* lw  = (const float*)d_in[1];
    const float* lb  = (const float*)d_in[2];
    const float* wih = (const float*)d_in[3];
    const float* whh = (const float*)d_in[4];
    const float* bih = (const float*)d_in[5];
    const float* bhh = (const float*)d_in[6];
    const float* ow  = (const float*)d_in[7];
    const float* ob  = (const float*)d_in[8];
    float* out = (float*)d_out;

    float *cb, *xp, *gx0, *ys;
    uint32_t *hb32, *wib32, *whb32;
    cudaGetSymbolAddress((void**)&cb,    g_c);
    cudaGetSymbolAddress((void**)&xp,    g_xp);
    cudaGetSymbolAddress((void**)&gx0,   g_gx0);
    cudaGetSymbolAddress((void**)&ys,    g_ys);
    cudaGetSymbolAddress((void**)&hb32,  g_hb32);
    cudaGetSymbolAddress((void**)&wib32, g_wib32);
    cudaGetSymbolAddress((void**)&whb32, g_whb32);

    cudaFuncSetAttribute(cell_diag_kernel, cudaFuncAttributeMaxDynamicSharedMemorySize, SM_BYTES);

    // ---- state init + weight conversion (graph nodes, deterministic) ----
    zero_kernel<<<2048, 256>>>((float*)hb32, LL * BB * HH);   // bf16 zeros (whole parity-buffered state)
    zero_kernel<<<2048, 256>>>(cb, LL * BB * HH);
    f2bf_kernel<<<1024, 256>>>(wih, wib32, LL * G4 * HH / 2);
    f2bf_kernel<<<1024, 256>>>(whh, whb32, LL * G4 * HH / 2);

    // xp = x @ lw.T + lb
    gemm_bias_kernel<false><<<dim3(HH / 64, BB / 64), 256>>>(x, lw, lb, xp, BB, HH, LATENT, HH);
    // gx0 = xp @ wih[0].T + bih[0]  (constant over time, fp32)
    gemm_bias_kernel<false><<<dim3(G4 / 64, BB / 64), 256>>>(xp, wih, bih, gx0, BB, G4, HH, G4);

    // ---- wavefront over diagonals k = l + t ----
    for (int k = 0; k < TT + LL - 1; ++k) {
        int lmin = k - (TT - 1); if (lmin < 0) lmin = 0;
        int lmax = k;            if (lmax > LL - 1) lmax = LL - 1;
        dim3 grid(4, 32, (unsigned)(lmax - lmin + 1));
        cell_diag_kernel<<<grid, 512, SM_BYTES>>>(k, lmin, bih, bhh);
    }

    // out = sigmoid(ys @ ow.T + ob)
    gemm_bias_kernel<true><<<dim3((OUTN + 63) / 64, (BB * TT) / 64), 256>>>(
        ys, ow, ob, out, BB * TT, OUTN, HH, OUTN);
}